// round 7
// baseline (speedup 1.0000x reference)
#include <cuda_runtime.h>
#include <cuda_bf16.h>
#include <cstdint>

// Problem constants
#define NN   20000
#define EE   640000
#define F0   128
#define F1   256
#define F2   128
#define NPAD 20096   // 157 * 128

// ---------------- scratch (device globals, zero at module load) -------------
__device__ __align__(16) float g_deg[NPAD];
__device__ __align__(16) int   g_cnt[NPAD];
__device__ __align__(16) int   g_pos[EE];             // per-edge slot within dst
__device__ __align__(16) int   g_off[NN + 1];
__device__ __align__(16) int2  g_pack[EE];            // (src_row, w_norm) by dst
__device__ __align__(16) float g_TxA[4 * NPAD * F0];  // layer1 Cheb stack + layer2 temps
__device__ __align__(16) float g_out1[NPAD * F1];
__device__ __align__(16) float g_Ck[4 * NPAD * F2];   // layer2 Horner coefficients
__device__ __align__(16) float g_out2[NPAD * F2];
__device__ __align__(16) float g_W2c[4 * F1 * F2];    // precombined layer2 weights
__device__ __align__(16) float g_stats[2 * F1];
__device__ __align__(16) float g_scale[F1];
__device__ __align__(16) float g_shift[F1];

// ---------------- CSR build --------------------------------------------------
__global__ void deg_cnt_kernel(const int* __restrict__ row,
                               const int* __restrict__ col,
                               const float* __restrict__ ew) {
    int e = blockIdx.x * blockDim.x + threadIdx.x;
    if (e >= EE) return;
    int r = row[e], c = col[e];
    float w = (r == c) ? 0.f : ew[e];
    if (w != 0.f) atomicAdd(&g_deg[r], w);
    g_pos[e] = atomicAdd(&g_cnt[c], 1);
}

// fused: dis = rsqrt(deg), then exclusive scan of counts -> offsets
__global__ void scan_dis_kernel() {
    int tid = threadIdx.x;
    for (int i = tid; i < NN; i += 1024) {
        float d = g_deg[i];
        g_deg[i] = (d > 0.f) ? rsqrtf(d) : 0.f;
    }
    const int PER = 20;   // 1024*20 >= NN+1
    int base = tid * PER;
    int v[PER];
    int s = 0;
#pragma unroll
    for (int j = 0; j < PER; j++) {
        int idx = base + j;
        int t = (idx < NN) ? g_cnt[idx] : 0;
        v[j] = t;
        s += t;
    }
    int lane = tid & 31, warp = tid >> 5;
    int p = s;
#pragma unroll
    for (int o = 1; o < 32; o <<= 1) {
        int t = __shfl_up_sync(0xffffffffu, p, o);
        if (lane >= o) p += t;
    }
    __shared__ int wsum[32];
    if (lane == 31) wsum[warp] = p;
    __syncthreads();
    if (warp == 0) {
        int q = wsum[lane];
#pragma unroll
        for (int o = 1; o < 32; o <<= 1) {
            int t = __shfl_up_sync(0xffffffffu, q, o);
            if (lane >= o) q += t;
        }
        wsum[lane] = q;
    }
    __syncthreads();
    int run = p - s + (warp ? wsum[warp - 1] : 0);
#pragma unroll
    for (int j = 0; j < PER; j++) {
        int idx = base + j;
        if (idx <= NN) g_off[idx] = run;
        run += v[j];
    }
}

// atomic-free scatter: slot precomputed in g_pos
__global__ void scatter_kernel(const int* __restrict__ row,
                               const int* __restrict__ col,
                               const float* __restrict__ ew) {
    int e = blockIdx.x * blockDim.x + threadIdx.x;
    if (e >= EE) return;
    int r = row[e], c = col[e];
    float w = (r == c) ? 0.f : ew[e];
    float wn = -g_deg[r] * w * g_deg[c];
    int2 p;
    p.x = r;
    p.y = __float_as_int(wn);
    g_pack[g_off[c] + g_pos[e]] = p;
}

// ---- gather SPMM (F=128): out = alpha*(L@in) - sub + add --------------------
__device__ __forceinline__ void spmm_fma(float4& acc, float w, const float4& v) {
    acc.x = fmaf(w, v.x, acc.x);
    acc.y = fmaf(w, v.y, acc.y);
    acc.z = fmaf(w, v.z, acc.z);
    acc.w = fmaf(w, v.w, acc.w);
}

__global__ void spmm_gather(const float* __restrict__ in, float* __restrict__ out,
                            const float* __restrict__ sub,
                            const float* __restrict__ add, float alpha) {
    int node = (blockIdx.x * blockDim.x + threadIdx.x) >> 5;
    if (node >= NN) return;
    int lane = threadIdx.x & 31;
    int beg = g_off[node], end = g_off[node + 1];

    const float4* base = (const float4*)in + lane;
    float4 acc0 = make_float4(0.f, 0.f, 0.f, 0.f);
    float4 acc1 = make_float4(0.f, 0.f, 0.f, 0.f);
    float4 acc2 = make_float4(0.f, 0.f, 0.f, 0.f);
    float4 acc3 = make_float4(0.f, 0.f, 0.f, 0.f);

    int i = beg;
    for (; i + 8 <= end; i += 8) {
        int2 p0 = g_pack[i + 0], p1 = g_pack[i + 1];
        int2 p2 = g_pack[i + 2], p3 = g_pack[i + 3];
        int2 p4 = g_pack[i + 4], p5 = g_pack[i + 5];
        int2 p6 = g_pack[i + 6], p7 = g_pack[i + 7];
        float4 v0 = base[(size_t)p0.x * 32];
        float4 v1 = base[(size_t)p1.x * 32];
        float4 v2 = base[(size_t)p2.x * 32];
        float4 v3 = base[(size_t)p3.x * 32];
        float4 v4 = base[(size_t)p4.x * 32];
        float4 v5 = base[(size_t)p5.x * 32];
        float4 v6 = base[(size_t)p6.x * 32];
        float4 v7 = base[(size_t)p7.x * 32];
        spmm_fma(acc0, __int_as_float(p0.y), v0);
        spmm_fma(acc1, __int_as_float(p1.y), v1);
        spmm_fma(acc2, __int_as_float(p2.y), v2);
        spmm_fma(acc3, __int_as_float(p3.y), v3);
        spmm_fma(acc0, __int_as_float(p4.y), v4);
        spmm_fma(acc1, __int_as_float(p5.y), v5);
        spmm_fma(acc2, __int_as_float(p6.y), v6);
        spmm_fma(acc3, __int_as_float(p7.y), v7);
    }
    for (; i + 2 <= end; i += 2) {
        int2 p0 = g_pack[i], p1 = g_pack[i + 1];
        float4 v0 = base[(size_t)p0.x * 32];
        float4 v1 = base[(size_t)p1.x * 32];
        spmm_fma(acc0, __int_as_float(p0.y), v0);
        spmm_fma(acc1, __int_as_float(p1.y), v1);
    }
    if (i < end) {
        int2 p0 = g_pack[i];
        float4 v0 = base[(size_t)p0.x * 32];
        spmm_fma(acc0, __int_as_float(p0.y), v0);
    }
    float4 r;
    r.x = alpha * ((acc0.x + acc1.x) + (acc2.x + acc3.x));
    r.y = alpha * ((acc0.y + acc1.y) + (acc2.y + acc3.y));
    r.z = alpha * ((acc0.z + acc1.z) + (acc2.z + acc3.z));
    r.w = alpha * ((acc0.w + acc1.w) + (acc2.w + acc3.w));
    size_t oidx = (size_t)node * 32 + lane;
    if (add) {
        float4 av = ((const float4*)add)[oidx];
        r.x += av.x; r.y += av.y; r.z += av.z; r.w += av.w;
    }
    if (sub) {
        float4 sv = ((const float4*)sub)[oidx];
        r.x -= sv.x; r.y -= sv.y; r.z -= sv.z; r.w -= sv.w;
    }
    ((float4*)out)[oidx] = r;
}

// ---------------- TF32 helpers ----------------------------------------------
__device__ __forceinline__ unsigned f2tf32(float f) {
    unsigned u;
    asm("cvt.rna.tf32.f32 %0, %1;" : "=r"(u) : "f"(f));
    return u;
}
#define AS_PITCH 36
#define BS_PITCH 132

// ---- GEMM1: out1 = sum_chunk TxA_chunk[NPAD][128] @ W1_chunk[128][256] + b1 -
__global__ __launch_bounds__(256)
void gemm1_tf32(const float* __restrict__ A, const float* __restrict__ W,
                const float* __restrict__ bias, float* __restrict__ C) {
    const int FIN = F0, FOUTT = F1;
    __shared__ unsigned As[128 * AS_PITCH];
    __shared__ unsigned Bs[32 * BS_PITCH];

    const int tid = threadIdx.x;
    const int lane = tid & 31;
    const int wid = tid >> 5;
    const int warp_m = wid >> 2;
    const int warp_n = wid & 3;
    const int bm = blockIdx.x * 128;
    const int bn = blockIdx.y * 128;

    float acc[4][4][4];
#pragma unroll
    for (int i = 0; i < 4; i++)
#pragma unroll
        for (int j = 0; j < 4; j++)
#pragma unroll
            for (int q = 0; q < 4; q++) acc[i][j][q] = 0.f;

    const unsigned asBase = __cvta_generic_to_shared(
        &As[(warp_m * 64 + (lane & 15)) * AS_PITCH + (lane >> 4) * 4]);

#pragma unroll 1
    for (int chunk = 0; chunk < 4; ++chunk) {
        const float* Ab = A + (size_t)chunk * NPAD * FIN;
        const float* Wb = W + (size_t)chunk * FIN * FOUTT;
#pragma unroll 1
        for (int k0 = 0; k0 < FIN; k0 += 32) {
            {
                int m = tid >> 3;
                int kg = (tid & 7) * 4;
#pragma unroll
                for (int p = 0; p < 4; ++p) {
                    int mr = m + p * 32;
                    float4 v = *(const float4*)(Ab + (size_t)(bm + mr) * FIN + k0 + kg);
                    unsigned* d = &As[mr * AS_PITCH + kg];
                    d[0] = f2tf32(v.x); d[1] = f2tf32(v.y);
                    d[2] = f2tf32(v.z); d[3] = f2tf32(v.w);
                }
            }
            {
                int k = tid >> 5;
                int n4 = (tid & 31) * 4;
#pragma unroll
                for (int p = 0; p < 4; ++p) {
                    int kr = k + p * 8;
                    float4 v = *(const float4*)(Wb + (size_t)(k0 + kr) * FOUTT + bn + n4);
                    unsigned* d = &Bs[kr * BS_PITCH + n4];
                    d[0] = f2tf32(v.x); d[1] = f2tf32(v.y);
                    d[2] = f2tf32(v.z); d[3] = f2tf32(v.w);
                }
            }
            __syncthreads();
#pragma unroll
            for (int k8 = 0; k8 < 4; ++k8) {
                unsigned a[4][4];
#pragma unroll
                for (int ms = 0; ms < 4; ++ms) {
                    unsigned addr = asBase + (ms * 16 * AS_PITCH + k8 * 8) * 4;
                    asm volatile(
                        "ldmatrix.sync.aligned.m8n8.x4.shared.b16 {%0,%1,%2,%3}, [%4];"
                        : "=r"(a[ms][0]), "=r"(a[ms][1]), "=r"(a[ms][2]), "=r"(a[ms][3])
                        : "r"(addr));
                }
                unsigned b0[4], b1[4];
                {
                    int bRow = k8 * 8 + (lane & 3);
                    int bCol = warp_n * 32 + (lane >> 2);
#pragma unroll
                    for (int ns = 0; ns < 4; ++ns) {
                        b0[ns] = Bs[bRow * BS_PITCH + bCol + ns * 8];
                        b1[ns] = Bs[(bRow + 4) * BS_PITCH + bCol + ns * 8];
                    }
                }
#pragma unroll
                for (int ms = 0; ms < 4; ++ms)
#pragma unroll
                    for (int ns = 0; ns < 4; ++ns) {
                        asm volatile(
                            "mma.sync.aligned.m16n8k8.row.col.f32.tf32.tf32.f32 "
                            "{%0,%1,%2,%3}, {%4,%5,%6,%7}, {%8,%9}, {%0,%1,%2,%3};"
                            : "+f"(acc[ms][ns][0]), "+f"(acc[ms][ns][1]),
                              "+f"(acc[ms][ns][2]), "+f"(acc[ms][ns][3])
                            : "r"(a[ms][0]), "r"(a[ms][1]), "r"(a[ms][2]), "r"(a[ms][3]),
                              "r"(b0[ns]), "r"(b1[ns]));
                    }
            }
            __syncthreads();
        }
    }
#pragma unroll
    for (int ms = 0; ms < 4; ++ms) {
        int r0 = bm + warp_m * 64 + ms * 16 + (lane >> 2);
#pragma unroll
        for (int ns = 0; ns < 4; ++ns) {
            int cc = bn + warp_n * 32 + ns * 8 + 2 * (lane & 3);
            float2 v0, v1;
            v0.x = acc[ms][ns][0] + bias[cc + 0];
            v0.y = acc[ms][ns][1] + bias[cc + 1];
            v1.x = acc[ms][ns][2] + bias[cc + 0];
            v1.y = acc[ms][ns][3] + bias[cc + 1];
            *(float2*)(C + (size_t)r0 * FOUTT + cc) = v0;
            *(float2*)(C + (size_t)(r0 + 8) * FOUTT + cc) = v1;
        }
    }
}

// ---- weight precombine for layer-2 Horner form ------------------------------
__global__ void wcomb_kernel(const float* __restrict__ W2) {
    int i = blockIdx.x * blockDim.x + threadIdx.x;
    const int SZ = F1 * F2;
    if (i >= SZ) return;
    float w0 = W2[i], w1 = W2[SZ + i], w2 = W2[2 * SZ + i], w3 = W2[3 * SZ + i];
    g_W2c[i]          = w0 - w2;
    g_W2c[SZ + i]     = w1 - 3.f * w3;
    g_W2c[2 * SZ + i] = 2.f * w2;
    g_W2c[3 * SZ + i] = 4.f * w3;
}

// ---- GEMM2: C_k = BNrelu(out1) @ W2c_k (+ b2 for k=0), k = blockIdx.y -------
__global__ __launch_bounds__(256)
void gemm2_tf32(const float* __restrict__ A, const float* __restrict__ bias) {
    const int FIN = F1, FOUTT = F2;
    __shared__ unsigned As[128 * AS_PITCH];
    __shared__ unsigned Bs[32 * BS_PITCH];

    const int tid = threadIdx.x;
    const int lane = tid & 31;
    const int wid = tid >> 5;
    const int warp_m = wid >> 2;
    const int warp_n = wid & 3;
    const int bm = blockIdx.x * 128;
    const int kblk = blockIdx.y;
    const float* Wb = g_W2c + (size_t)kblk * FIN * FOUTT;
    float* C = g_Ck + (size_t)kblk * NPAD * FOUTT;

    float acc[4][4][4];
#pragma unroll
    for (int i = 0; i < 4; i++)
#pragma unroll
        for (int j = 0; j < 4; j++)
#pragma unroll
            for (int q = 0; q < 4; q++) acc[i][j][q] = 0.f;

    const unsigned asBase = __cvta_generic_to_shared(
        &As[(warp_m * 64 + (lane & 15)) * AS_PITCH + (lane >> 4) * 4]);

#pragma unroll 1
    for (int k0 = 0; k0 < FIN; k0 += 32) {
        {
            int m = tid >> 3;
            int kg = (tid & 7) * 4;
            float4 sc = *(const float4*)&g_scale[k0 + kg];
            float4 sh = *(const float4*)&g_shift[k0 + kg];
#pragma unroll
            for (int p = 0; p < 4; ++p) {
                int mr = m + p * 32;
                float4 v = *(const float4*)(A + (size_t)(bm + mr) * FIN + k0 + kg);
                v.x = fmaf(fmaxf(v.x, 0.f), sc.x, sh.x);
                v.y = fmaf(fmaxf(v.y, 0.f), sc.y, sh.y);
                v.z = fmaf(fmaxf(v.z, 0.f), sc.z, sh.z);
                v.w = fmaf(fmaxf(v.w, 0.f), sc.w, sh.w);
                unsigned* d = &As[mr * AS_PITCH + kg];
                d[0] = f2tf32(v.x); d[1] = f2tf32(v.y);
                d[2] = f2tf32(v.z); d[3] = f2tf32(v.w);
            }
        }
        {
            int k = tid >> 5;
            int n4 = (tid & 31) * 4;
#pragma unroll
            for (int p = 0; p < 4; ++p) {
                int kr = k + p * 8;
                float4 v = *(const float4*)(Wb + (size_t)(k0 + kr) * FOUTT + n4);
                unsigned* d = &Bs[kr * BS_PITCH + n4];
                d[0] = f2tf32(v.x); d[1] = f2tf32(v.y);
                d[2] = f2tf32(v.z); d[3] = f2tf32(v.w);
            }
        }
        __syncthreads();
#pragma unroll
        for (int k8 = 0; k8 < 4; ++k8) {
            unsigned a[4][4];
#pragma unroll
            for (int ms = 0; ms < 4; ++ms) {
                unsigned addr = asBase + (ms * 16 * AS_PITCH + k8 * 8) * 4;
                asm volatile(
                    "ldmatrix.sync.aligned.m8n8.x4.shared.b16 {%0,%1,%2,%3}, [%4];"
                    : "=r"(a[ms][0]), "=r"(a[ms][1]), "=r"(a[ms][2]), "=r"(a[ms][3])
                    : "r"(addr));
            }
            unsigned b0[4], b1[4];
            {
                int bRow = k8 * 8 + (lane & 3);
                int bCol = warp_n * 32 + (lane >> 2);
#pragma unroll
                for (int ns = 0; ns < 4; ++ns) {
                    b0[ns] = Bs[bRow * BS_PITCH + bCol + ns * 8];
                    b1[ns] = Bs[(bRow + 4) * BS_PITCH + bCol + ns * 8];
                }
            }
#pragma unroll
            for (int ms = 0; ms < 4; ++ms)
#pragma unroll
                for (int ns = 0; ns < 4; ++ns) {
                    asm volatile(
                        "mma.sync.aligned.m16n8k8.row.col.f32.tf32.tf32.f32 "
                        "{%0,%1,%2,%3}, {%4,%5,%6,%7}, {%8,%9}, {%0,%1,%2,%3};"
                        : "+f"(acc[ms][ns][0]), "+f"(acc[ms][ns][1]),
                          "+f"(acc[ms][ns][2]), "+f"(acc[ms][ns][3])
                        : "r"(a[ms][0]), "r"(a[ms][1]), "r"(a[ms][2]), "r"(a[ms][3]),
                          "r"(b0[ns]), "r"(b1[ns]));
                }
        }
        __syncthreads();
    }
    bool addb = (kblk == 0);
#pragma unroll
    for (int ms = 0; ms < 4; ++ms) {
        int r0 = bm + warp_m * 64 + ms * 16 + (lane >> 2);
#pragma unroll
        for (int ns = 0; ns < 4; ++ns) {
            int cc = warp_n * 32 + ns * 8 + 2 * (lane & 3);
            float bx = addb ? bias[cc + 0] : 0.f;
            float by = addb ? bias[cc + 1] : 0.f;
            float2 v0, v1;
            v0.x = acc[ms][ns][0] + bx;
            v0.y = acc[ms][ns][1] + by;
            v1.x = acc[ms][ns][2] + bx;
            v1.y = acc[ms][ns][3] + by;
            *(float2*)(C + (size_t)r0 * FOUTT + cc) = v0;
            *(float2*)(C + (size_t)(r0 + 8) * FOUTT + cc) = v1;
        }
    }
}

// ---------------- BN stats (relu fused) --------------------------------------
template <int F>
__global__ void stats_kernel(const float* __restrict__ X) {
    int col = threadIdx.x & (F - 1);
    int ro = threadIdx.x / F;
    int rstep = 256 / F;
    int r0 = blockIdx.x * 128 + ro;
    int rend = blockIdx.x * 128 + 128;
    if (rend > NN) rend = NN;
    float s = 0.f, s2 = 0.f;
    for (int r = r0; r < rend; r += rstep) {
        float v = X[(size_t)r * F + col];
        v = v > 0.f ? v : 0.f;
        s += v;
        s2 = fmaf(v, v, s2);
    }
    atomicAdd(&g_stats[col], s);
    atomicAdd(&g_stats[F + col], s2);
}

__global__ void scaleshift_kernel(const float* __restrict__ gamma,
                                  const float* __restrict__ beta, int F) {
    int c = threadIdx.x;
    if (c >= F) return;
    float m = g_stats[c] / (float)NN;
    float v = g_stats[F + c] / (float)NN - m * m;
    float inv = rsqrtf(v + 1e-5f);
    float sc = gamma[c] * inv;
    g_scale[c] = sc;
    g_shift[c] = beta[c] - m * sc;
}

// ---- final: out = BNrelu(out2) @ Wlin^T + blin, warp per node ---------------
__global__ void final_kernel(const float* __restrict__ h, const float* __restrict__ Wl,
                             const float* __restrict__ bl, float* __restrict__ out) {
    int node = (blockIdx.x * blockDim.x + threadIdx.x) >> 5;
    if (node >= NN) return;
    int lane = threadIdx.x & 31;
    float4 v = ((const float4*)(h + (size_t)node * F2))[lane];
    int c = lane * 4;
    float h0 = fmaf(fmaxf(v.x, 0.f), g_scale[c + 0], g_shift[c + 0]);
    float h1 = fmaf(fmaxf(v.y, 0.f), g_scale[c + 1], g_shift[c + 1]);
    float h2 = fmaf(fmaxf(v.z, 0.f), g_scale[c + 2], g_shift[c + 2]);
    float h3 = fmaf(fmaxf(v.w, 0.f), g_scale[c + 3], g_shift[c + 3]);
#pragma unroll
    for (int o = 0; o < 10; ++o) {
        float4 w = ((const float4*)(Wl + o * F2))[lane];
        float p = h0 * w.x + h1 * w.y + h2 * w.z + h3 * w.w;
        p += __shfl_xor_sync(0xffffffffu, p, 16);
        p += __shfl_xor_sync(0xffffffffu, p, 8);
        p += __shfl_xor_sync(0xffffffffu, p, 4);
        p += __shfl_xor_sync(0xffffffffu, p, 2);
        p += __shfl_xor_sync(0xffffffffu, p, 1);
        if (lane == 0) out[node * 10 + o] = p + bl[o];
    }
}

// ---------------- launch ------------------------------------------------------
extern "C" void kernel_launch(void* const* d_in, const int* in_sizes, int n_in,
                              void* d_out, int out_size) {
    const float* x      = (const float*)d_in[0];
    const int*   ei     = (const int*)d_in[1];
    const float* ew     = (const float*)d_in[2];
    const float* W1     = (const float*)d_in[3];
    const float* b1     = (const float*)d_in[4];
    const float* W2     = (const float*)d_in[5];
    const float* b2     = (const float*)d_in[6];
    const float* gamma1 = (const float*)d_in[7];
    const float* beta1  = (const float*)d_in[8];
    const float* gamma2 = (const float*)d_in[9];
    const float* beta2  = (const float*)d_in[10];
    const float* Wlin   = (const float*)d_in[11];
    const float* blin   = (const float*)d_in[12];
    float* out = (float*)d_out;

    const int* row = ei;
    const int* col = ei + EE;

    float *deg, *TxA, *out1, *Ck, *out2, *stats;
    int *cnt;
    cudaGetSymbolAddress((void**)&deg,   g_deg);
    cudaGetSymbolAddress((void**)&cnt,   g_cnt);
    cudaGetSymbolAddress((void**)&TxA,   g_TxA);
    cudaGetSymbolAddress((void**)&out1,  g_out1);
    cudaGetSymbolAddress((void**)&Ck,    g_Ck);
    cudaGetSymbolAddress((void**)&out2,  g_out2);
    cudaGetSymbolAddress((void**)&stats, g_stats);

    const int EB = (EE + 255) / 256;
    const int SB = (NN * 32 + 255) / 256;   // warp-per-node grids

    // ---- CSR build ----
    cudaMemsetAsync(deg, 0, NPAD * sizeof(float));
    cudaMemsetAsync(cnt, 0, NPAD * sizeof(int));
    cudaMemsetAsync(stats, 0, 2 * F1 * sizeof(float));

    deg_cnt_kernel<<<EB, 256>>>(row, col, ew);
    scan_dis_kernel<<<1, 1024>>>();
    scatter_kernel<<<EB, 256>>>(row, col, ew);

    cudaMemcpyAsync(TxA, x, (size_t)NN * F0 * sizeof(float), cudaMemcpyDeviceToDevice);

    // ---- layer 1: Chebyshev recursion at F=128 ----
    float* A0 = TxA;
    float* A1 = TxA + (size_t)NPAD * F0;
    float* A2 = TxA + (size_t)2 * NPAD * F0;
    float* A3 = TxA + (size_t)3 * NPAD * F0;
    spmm_gather<<<SB, 256>>>(A0, A1, nullptr, nullptr, 1.f);
    spmm_gather<<<SB, 256>>>(A1, A2, A0, nullptr, 2.f);
    spmm_gather<<<SB, 256>>>(A2, A3, A1, nullptr, 2.f);

    gemm1_tf32<<<dim3(NPAD / 128, 2), 256>>>(TxA, W1, b1, out1);

    stats_kernel<F1><<<157, 256>>>(out1);
    scaleshift_kernel<<<1, 256>>>(gamma1, beta1, F1);
    cudaMemsetAsync(stats, 0, 2 * F1 * sizeof(float));

    // ---- layer 2: Horner form ----
    wcomb_kernel<<<(F1 * F2 + 255) / 256, 256>>>(W2);
    gemm2_tf32<<<dim3(NPAD / 128, 4), 256>>>(out1, b2);

    float* C0 = Ck;
    float* C1 = Ck + (size_t)NPAD * F2;
    float* C2 = Ck + (size_t)2 * NPAD * F2;
    float* C3 = Ck + (size_t)3 * NPAD * F2;
    float* t1 = TxA;
    float* t2 = TxA + (size_t)NPAD * F0;
    spmm_gather<<<SB, 256>>>(C3, t1, nullptr, C2, 1.f);
    spmm_gather<<<SB, 256>>>(t1, t2, nullptr, C1, 1.f);
    spmm_gather<<<SB, 256>>>(t2, out2, nullptr, C0, 1.f);

    stats_kernel<F2><<<157, 256>>>(out2);
    scaleshift_kernel<<<1, 128>>>(gamma2, beta2, F2);

    final_kernel<<<SB, 256>>>(out2, Wlin, blin, out);
}

// round 8
// speedup vs baseline: 1.2420x; 1.2420x over previous
#include <cuda_runtime.h>
#include <cuda_fp16.h>
#include <cstdint>

// Problem constants
#define NN   20000
#define EE   640000
#define F0   128
#define F1   256
#define F2   128
#define NPAD 20096   // 157 * 128

// ---------------- scratch (device globals, zero at module load) -------------
__device__ __align__(16) float  g_deg[NPAD];
__device__ __align__(16) int    g_cnt[NPAD];
__device__ __align__(16) int    g_pos[EE];
__device__ __align__(16) int    g_off[NN + 1];
__device__ __align__(16) int2   g_pack[EE];             // (src_row, w_norm) by dst
__device__ __align__(16) __half g_TxA[4 * NPAD * F0];   // fp16 feature stacks
__device__ __align__(16) float  g_out1[NPAD * F1];      // GEMM1 out (fp32)
__device__ __align__(16) __half g_Ck[4 * NPAD * F2];    // layer2 Horner coeffs
__device__ __align__(16) __half g_out2[NPAD * F2];
__device__ __align__(16) float  g_W2c[4 * F1 * F2];
__device__ __align__(16) float  g_stats[2 * F1];
__device__ __align__(16) float  g_scale[F1];
__device__ __align__(16) float  g_shift[F1];

// ---------------- CSR build --------------------------------------------------
__global__ void deg_cnt_kernel(const int* __restrict__ row,
                               const int* __restrict__ col,
                               const float* __restrict__ ew) {
    int e = blockIdx.x * blockDim.x + threadIdx.x;
    if (e >= EE) return;
    int r = row[e], c = col[e];
    float w = (r == c) ? 0.f : ew[e];
    if (w != 0.f) atomicAdd(&g_deg[r], w);
    g_pos[e] = atomicAdd(&g_cnt[c], 1);
}

__global__ void scan_dis_kernel() {
    int tid = threadIdx.x;
    for (int i = tid; i < NN; i += 1024) {
        float d = g_deg[i];
        g_deg[i] = (d > 0.f) ? rsqrtf(d) : 0.f;
    }
    const int PER = 20;
    int base = tid * PER;
    int v[PER];
    int s = 0;
#pragma unroll
    for (int j = 0; j < PER; j++) {
        int idx = base + j;
        int t = (idx < NN) ? g_cnt[idx] : 0;
        v[j] = t;
        s += t;
    }
    int lane = tid & 31, warp = tid >> 5;
    int p = s;
#pragma unroll
    for (int o = 1; o < 32; o <<= 1) {
        int t = __shfl_up_sync(0xffffffffu, p, o);
        if (lane >= o) p += t;
    }
    __shared__ int wsum[32];
    if (lane == 31) wsum[warp] = p;
    __syncthreads();
    if (warp == 0) {
        int q = wsum[lane];
#pragma unroll
        for (int o = 1; o < 32; o <<= 1) {
            int t = __shfl_up_sync(0xffffffffu, q, o);
            if (lane >= o) q += t;
        }
        wsum[lane] = q;
    }
    __syncthreads();
    int run = p - s + (warp ? wsum[warp - 1] : 0);
#pragma unroll
    for (int j = 0; j < PER; j++) {
        int idx = base + j;
        if (idx <= NN) g_off[idx] = run;
        run += v[j];
    }
}

__global__ void scatter_kernel(const int* __restrict__ row,
                               const int* __restrict__ col,
                               const float* __restrict__ ew) {
    int e = blockIdx.x * blockDim.x + threadIdx.x;
    if (e >= EE) return;
    int r = row[e], c = col[e];
    float w = (r == c) ? 0.f : ew[e];
    float wn = -g_deg[r] * w * g_deg[c];
    int2 p;
    p.x = r;
    p.y = __float_as_int(wn);
    g_pack[g_off[c] + g_pos[e]] = p;
}

// x (fp32) -> A0 (fp16)
__global__ void cvt_x_kernel(const float* __restrict__ x, __half* __restrict__ dst) {
    int i = blockIdx.x * blockDim.x + threadIdx.x;
    if (i >= NN * 32) return;
    float4 v = ((const float4*)x)[i];
    uint2 o;
    __half2 h0 = __floats2half2_rn(v.x, v.y);
    __half2 h1 = __floats2half2_rn(v.z, v.w);
    o.x = *(unsigned*)&h0;
    o.y = *(unsigned*)&h1;
    ((uint2*)dst)[i] = o;
}

// ---- gather SPMM (fp16, F=128): out = alpha*(L@in) - sub + add --------------
__device__ __forceinline__ void hfma4(float4& acc, float w, uint2 u) {
    float2 f0 = __half22float2(*(__half2*)&u.x);
    float2 f1 = __half22float2(*(__half2*)&u.y);
    acc.x = fmaf(w, f0.x, acc.x);
    acc.y = fmaf(w, f0.y, acc.y);
    acc.z = fmaf(w, f1.x, acc.z);
    acc.w = fmaf(w, f1.y, acc.w);
}

__global__ void spmm_h(const __half* __restrict__ in, __half* __restrict__ out,
                       const __half* __restrict__ sub,
                       const __half* __restrict__ add, float alpha) {
    int node = (blockIdx.x * blockDim.x + threadIdx.x) >> 5;
    if (node >= NN) return;
    int lane = threadIdx.x & 31;
    int beg = g_off[node], end = g_off[node + 1];

    const uint2* base = (const uint2*)in + lane;   // 32 uint2 per 128-half row
    float4 acc0 = make_float4(0.f, 0.f, 0.f, 0.f);
    float4 acc1 = make_float4(0.f, 0.f, 0.f, 0.f);
    float4 acc2 = make_float4(0.f, 0.f, 0.f, 0.f);
    float4 acc3 = make_float4(0.f, 0.f, 0.f, 0.f);

    int i = beg;
    for (; i + 4 <= end; i += 4) {
        int2 p0 = g_pack[i + 0], p1 = g_pack[i + 1];
        int2 p2 = g_pack[i + 2], p3 = g_pack[i + 3];
        uint2 u0 = base[(size_t)p0.x * 32];
        uint2 u1 = base[(size_t)p1.x * 32];
        uint2 u2 = base[(size_t)p2.x * 32];
        uint2 u3 = base[(size_t)p3.x * 32];
        hfma4(acc0, __int_as_float(p0.y), u0);
        hfma4(acc1, __int_as_float(p1.y), u1);
        hfma4(acc2, __int_as_float(p2.y), u2);
        hfma4(acc3, __int_as_float(p3.y), u3);
    }
    for (; i < end; ++i) {
        int2 p0 = g_pack[i];
        uint2 u0 = base[(size_t)p0.x * 32];
        hfma4(acc0, __int_as_float(p0.y), u0);
    }
    float4 r;
    r.x = alpha * ((acc0.x + acc1.x) + (acc2.x + acc3.x));
    r.y = alpha * ((acc0.y + acc1.y) + (acc2.y + acc3.y));
    r.z = alpha * ((acc0.z + acc1.z) + (acc2.z + acc3.z));
    r.w = alpha * ((acc0.w + acc1.w) + (acc2.w + acc3.w));
    size_t oidx = (size_t)node * 32 + lane;
    if (add) {
        uint2 u = ((const uint2*)add)[oidx];
        float2 f0 = __half22float2(*(__half2*)&u.x);
        float2 f1 = __half22float2(*(__half2*)&u.y);
        r.x += f0.x; r.y += f0.y; r.z += f1.x; r.w += f1.y;
    }
    if (sub) {
        uint2 u = ((const uint2*)sub)[oidx];
        float2 f0 = __half22float2(*(__half2*)&u.x);
        float2 f1 = __half22float2(*(__half2*)&u.y);
        r.x -= f0.x; r.y -= f0.y; r.z -= f1.x; r.w -= f1.y;
    }
    uint2 o;
    __half2 h0 = __floats2half2_rn(r.x, r.y);
    __half2 h1 = __floats2half2_rn(r.z, r.w);
    o.x = *(unsigned*)&h0;
    o.y = *(unsigned*)&h1;
    ((uint2*)out)[oidx] = o;
}

// ---------------- fp16 tensor-core GEMMs -------------------------------------
#define PA 40    // A smem pitch (halves)
#define PB 136   // B smem pitch (halves)

// GEMM1: out1[NPAD][256] = sum_chunk TxA_chunk[NPAD][128](h) @ W1_chunk[128][256](f) + b1
__global__ __launch_bounds__(256)
void gemm1_f16(const __half* __restrict__ A, const float* __restrict__ W,
               const float* __restrict__ bias, float* __restrict__ C) {
    __shared__ __align__(16) __half As[128 * PA];
    __shared__ __align__(16) __half Bs[32 * PB];

    const int tid = threadIdx.x;
    const int lane = tid & 31;
    const int wid = tid >> 5;
    const int warp_m = wid >> 2;
    const int warp_n = wid & 3;
    const int bm = blockIdx.x * 128;
    const int bn = blockIdx.y * 128;

    float acc[4][4][4];
#pragma unroll
    for (int i = 0; i < 4; i++)
#pragma unroll
        for (int j = 0; j < 4; j++)
#pragma unroll
            for (int q = 0; q < 4; q++) acc[i][j][q] = 0.f;

    const unsigned asBase = (unsigned)__cvta_generic_to_shared(
        &As[(warp_m * 64 + (lane & 15)) * PA + (lane >> 4) * 8]);
    const int b_k = ((lane >> 3) & 1) * 8 + (lane & 7);   // 0..15
    const int b_n = (lane >> 4) * 8;                      // 0 or 8

#pragma unroll 1
    for (int chunk = 0; chunk < 4; ++chunk) {
        const __half* Ab = A + (size_t)chunk * NPAD * F0;
        const float*  Wb = W + (size_t)chunk * F0 * F1;
#pragma unroll 1
        for (int k0 = 0; k0 < F0; k0 += 32) {
            {
                int m = tid >> 2;
                int kq = (tid & 3) * 8;
#pragma unroll
                for (int p = 0; p < 2; ++p) {
                    int rowm = m + p * 64;
                    uint4 v = *(const uint4*)(Ab + (size_t)(bm + rowm) * F0 + k0 + kq);
                    *(uint4*)&As[rowm * PA + kq] = v;
                }
            }
            {
                int kk = tid >> 5;
                int n4 = (tid & 31) * 4;
#pragma unroll
                for (int p = 0; p < 4; ++p) {
                    int kr = kk + p * 8;
                    float4 v = *(const float4*)(Wb + (size_t)(k0 + kr) * F1 + bn + n4);
                    __half2 h0 = __floats2half2_rn(v.x, v.y);
                    __half2 h1 = __floats2half2_rn(v.z, v.w);
                    uint2 o;
                    o.x = *(unsigned*)&h0;
                    o.y = *(unsigned*)&h1;
                    *(uint2*)&Bs[kr * PB + n4] = o;
                }
            }
            __syncthreads();
#pragma unroll
            for (int ks = 0; ks < 2; ++ks) {
                unsigned a[4][4];
#pragma unroll
                for (int ms = 0; ms < 4; ++ms) {
                    unsigned addr = asBase + ms * (16 * PA * 2) + ks * 32;
                    asm volatile(
                        "ldmatrix.sync.aligned.m8n8.x4.shared.b16 {%0,%1,%2,%3}, [%4];"
                        : "=r"(a[ms][0]), "=r"(a[ms][1]), "=r"(a[ms][2]), "=r"(a[ms][3])
                        : "r"(addr));
                }
                unsigned b[4][2];
#pragma unroll
                for (int nsp = 0; nsp < 2; ++nsp) {
                    int ncol = warp_n * 32 + nsp * 16 + b_n;
                    unsigned baddr = (unsigned)__cvta_generic_to_shared(
                        &Bs[(ks * 16 + b_k) * PB + ncol]);
                    asm volatile(
                        "ldmatrix.sync.aligned.m8n8.x4.trans.shared.b16 {%0,%1,%2,%3}, [%4];"
                        : "=r"(b[2 * nsp][0]), "=r"(b[2 * nsp][1]),
                          "=r"(b[2 * nsp + 1][0]), "=r"(b[2 * nsp + 1][1])
                        : "r"(baddr));
                }
#pragma unroll
                for (int ms = 0; ms < 4; ++ms)
#pragma unroll
                    for (int ns = 0; ns < 4; ++ns) {
                        asm volatile(
                            "mma.sync.aligned.m16n8k16.row.col.f32.f16.f16.f32 "
                            "{%0,%1,%2,%3}, {%4,%5,%6,%7}, {%8,%9}, {%0,%1,%2,%3};"
                            : "+f"(acc[ms][ns][0]), "+f"(acc[ms][ns][1]),
                              "+f"(acc[ms][ns][2]), "+f"(acc[ms][ns][3])
                            : "r"(a[ms][0]), "r"(a[ms][1]), "r"(a[ms][2]), "r"(a[ms][3]),
                              "r"(b[ns][0]), "r"(b[ns][1]));
                    }
            }
            __syncthreads();
        }
    }
#pragma unroll
    for (int ms = 0; ms < 4; ++ms) {
        int r0 = bm + warp_m * 64 + ms * 16 + (lane >> 2);
#pragma unroll
        for (int ns = 0; ns < 4; ++ns) {
            int cc = bn + warp_n * 32 + ns * 8 + 2 * (lane & 3);
            float2 v0, v1;
            v0.x = acc[ms][ns][0] + bias[cc + 0];
            v0.y = acc[ms][ns][1] + bias[cc + 1];
            v1.x = acc[ms][ns][2] + bias[cc + 0];
            v1.y = acc[ms][ns][3] + bias[cc + 1];
            *(float2*)(C + (size_t)r0 * F1 + cc) = v0;
            *(float2*)(C + (size_t)(r0 + 8) * F1 + cc) = v1;
        }
    }
}

// weight precombine for layer-2 Horner form
__global__ void wcomb_kernel(const float* __restrict__ W2) {
    int i = blockIdx.x * blockDim.x + threadIdx.x;
    const int SZ = F1 * F2;
    if (i >= SZ) return;
    float w0 = W2[i], w1 = W2[SZ + i], w2 = W2[2 * SZ + i], w3 = W2[3 * SZ + i];
    g_W2c[i]          = w0 - w2;
    g_W2c[SZ + i]     = w1 - 3.f * w3;
    g_W2c[2 * SZ + i] = 2.f * w2;
    g_W2c[3 * SZ + i] = 4.f * w3;
}

// GEMM2: C_k(h) = BNrelu(out1(f)) @ W2c_k (+ b2 for k=0); k = blockIdx.y
__global__ __launch_bounds__(256)
void gemm2_f16(const float* __restrict__ A, const float* __restrict__ bias) {
    __shared__ __align__(16) __half As[128 * PA];
    __shared__ __align__(16) __half Bs[32 * PB];

    const int tid = threadIdx.x;
    const int lane = tid & 31;
    const int wid = tid >> 5;
    const int warp_m = wid >> 2;
    const int warp_n = wid & 3;
    const int bm = blockIdx.x * 128;
    const int kblk = blockIdx.y;
    const float* Wb = g_W2c + (size_t)kblk * F1 * F2;
    __half* C = g_Ck + (size_t)kblk * NPAD * F2;

    float acc[4][4][4];
#pragma unroll
    for (int i = 0; i < 4; i++)
#pragma unroll
        for (int j = 0; j < 4; j++)
#pragma unroll
            for (int q = 0; q < 4; q++) acc[i][j][q] = 0.f;

    const unsigned asBase = (unsigned)__cvta_generic_to_shared(
        &As[(warp_m * 64 + (lane & 15)) * PA + (lane >> 4) * 8]);
    const int b_k = ((lane >> 3) & 1) * 8 + (lane & 7);
    const int b_n = (lane >> 4) * 8;

#pragma unroll 1
    for (int k0 = 0; k0 < F1; k0 += 32) {
        {
            int m = tid >> 2;
            int kq = (tid & 3) * 8;
            float4 sc0 = *(const float4*)&g_scale[k0 + kq];
            float4 sc1 = *(const float4*)&g_scale[k0 + kq + 4];
            float4 sh0 = *(const float4*)&g_shift[k0 + kq];
            float4 sh1 = *(const float4*)&g_shift[k0 + kq + 4];
#pragma unroll
            for (int p = 0; p < 2; ++p) {
                int rowm = m + p * 64;
                const float* ar = A + (size_t)(bm + rowm) * F1 + k0 + kq;
                float4 v0 = ((const float4*)ar)[0];
                float4 v1 = ((const float4*)ar)[1];
                v0.x = fmaf(fmaxf(v0.x, 0.f), sc0.x, sh0.x);
                v0.y = fmaf(fmaxf(v0.y, 0.f), sc0.y, sh0.y);
                v0.z = fmaf(fmaxf(v0.z, 0.f), sc0.z, sh0.z);
                v0.w = fmaf(fmaxf(v0.w, 0.f), sc0.w, sh0.w);
                v1.x = fmaf(fmaxf(v1.x, 0.f), sc1.x, sh1.x);
                v1.y = fmaf(fmaxf(v1.y, 0.f), sc1.y, sh1.y);
                v1.z = fmaf(fmaxf(v1.z, 0.f), sc1.z, sh1.z);
                v1.w = fmaf(fmaxf(v1.w, 0.f), sc1.w, sh1.w);
                __half2 h0 = __floats2half2_rn(v0.x, v0.y);
                __half2 h1 = __floats2half2_rn(v0.z, v0.w);
                __half2 h2 = __floats2half2_rn(v1.x, v1.y);
                __half2 h3 = __floats2half2_rn(v1.z, v1.w);
                uint4 o;
                o.x = *(unsigned*)&h0; o.y = *(unsigned*)&h1;
                o.z = *(unsigned*)&h2; o.w = *(unsigned*)&h3;
                *(uint4*)&As[rowm * PA + kq] = o;
            }
        }
        {
            int kk = tid >> 5;
            int n4 = (tid & 31) * 4;
#pragma unroll
            for (int p = 0; p < 4; ++p) {
                int kr = kk + p * 8;
                float4 v = *(const float4*)(Wb + (size_t)(k0 + kr) * F2 + n4);
                __half2 h0 = __floats2half2_rn(v.x, v.y);
                __half2 h1 = __floats2half2_rn(v.z, v.w);
                uint2 o;
                o.x = *(unsigned*)&h0;
                o.y = *(unsigned*)&h1;
                *(uint2*)&Bs[kr * PB + n4] = o;
            }
        }
        __syncthreads();
#pragma unroll
        for (int ks = 0; ks < 2; ++ks) {
            unsigned a[4][4];
#pragma unroll
            for (int ms = 0; ms < 4; ++ms) {
                unsigned addr = asBase + ms * (16 * PA * 2) + ks * 32;
                asm volatile(
                    "ldmatrix.sync.aligned.m8n8.x4.shared.b16 {%0,%1,%2,%3}, [%4];"
                    : "=r"(a[ms][0]), "=r"(a[ms][1]), "=r"(a[ms][2]), "=r"(a[ms][3])
                    : "r"(addr));
            }
            unsigned b[4][2];
#pragma unroll
            for (int nsp = 0; nsp < 2; ++nsp) {
                int ncol = warp_n * 32 + nsp * 16 + b_n;
                unsigned baddr = (unsigned)__cvta_generic_to_shared(
                    &Bs[(ks * 16 + b_k) * PB + ncol]);
                asm volatile(
                    "ldmatrix.sync.aligned.m8n8.x4.trans.shared.b16 {%0,%1,%2,%3}, [%4];"
                    : "=r"(b[2 * nsp][0]), "=r"(b[2 * nsp][1]),
                      "=r"(b[2 * nsp + 1][0]), "=r"(b[2 * nsp + 1][1])
                    : "r"(baddr));
            }
#pragma unroll
            for (int ms = 0; ms < 4; ++ms)
#pragma unroll
                for (int ns = 0; ns < 4; ++ns) {
                    asm volatile(
                        "mma.sync.aligned.m16n8k16.row.col.f32.f16.f16.f32 "
                        "{%0,%1,%2,%3}, {%4,%5,%6,%7}, {%8,%9}, {%0,%1,%2,%3};"
                        : "+f"(acc[ms][ns][0]), "+f"(acc[ms][ns][1]),
                          "+f"(acc[ms][ns][2]), "+f"(acc[ms][ns][3])
                        : "r"(a[ms][0]), "r"(a[ms][1]), "r"(a[ms][2]), "r"(a[ms][3]),
                          "r"(b[ns][0]), "r"(b[ns][1]));
                }
        }
        __syncthreads();
    }
    bool addb = (kblk == 0);
#pragma unroll
    for (int ms = 0; ms < 4; ++ms) {
        int r0 = bm + warp_m * 64 + ms * 16 + (lane >> 2);
#pragma unroll
        for (int ns = 0; ns < 4; ++ns) {
            int cc = warp_n * 32 + ns * 8 + 2 * (lane & 3);
            float bx = addb ? bias[cc + 0] : 0.f;
            float by = addb ? bias[cc + 1] : 0.f;
            __half2 h0 = __floats2half2_rn(acc[ms][ns][0] + bx, acc[ms][ns][1] + by);
            __half2 h1 = __floats2half2_rn(acc[ms][ns][2] + bx, acc[ms][ns][3] + by);
            *(__half2*)&C[(size_t)r0 * F2 + cc] = h0;
            *(__half2*)&C[(size_t)(r0 + 8) * F2 + cc] = h1;
        }
    }
}

// ---------------- BN stats ----------------------------------------------------
__global__ void stats_f256(const float* __restrict__ X) {
    int col = threadIdx.x;            // 256 threads = 256 cols
    int r0 = blockIdx.x * 128;
    int rend = r0 + 128;
    if (rend > NN) rend = NN;
    float s = 0.f, s2 = 0.f;
    for (int r = r0; r < rend; ++r) {
        float v = X[(size_t)r * F1 + col];
        v = v > 0.f ? v : 0.f;
        s += v;
        s2 = fmaf(v, v, s2);
    }
    atomicAdd(&g_stats[col], s);
    atomicAdd(&g_stats[F1 + col], s2);
}

__global__ void stats_h128(const __half* __restrict__ X) {
    int col = threadIdx.x & 127;
    int ro = threadIdx.x >> 7;        // 0..1
    int r0 = blockIdx.x * 128 + ro;
    int rend = blockIdx.x * 128 + 128;
    if (rend > NN) rend = NN;
    float s = 0.f, s2 = 0.f;
    for (int r = r0; r < rend; r += 2) {
        float v = __half2float(X[(size_t)r * F2 + col]);
        v = v > 0.f ? v : 0.f;
        s += v;
        s2 = fmaf(v, v, s2);
    }
    atomicAdd(&g_stats[col], s);
    atomicAdd(&g_stats[F2 + col], s2);
}

__global__ void scaleshift_kernel(const float* __restrict__ gamma,
                                  const float* __restrict__ beta, int F) {
    int c = threadIdx.x;
    if (c >= F) return;
    float m = g_stats[c] / (float)NN;
    float v = g_stats[F + c] / (float)NN - m * m;
    float inv = rsqrtf(v + 1e-5f);
    float sc = gamma[c] * inv;
    g_scale[c] = sc;
    g_shift[c] = beta[c] - m * sc;
}

// ---- final: out = BNrelu(out2(h)) @ Wlin^T + blin, warp per node ------------
__global__ void final_kernel(const __half* __restrict__ h, const float* __restrict__ Wl,
                             const float* __restrict__ bl, float* __restrict__ out) {
    int node = (blockIdx.x * blockDim.x + threadIdx.x) >> 5;
    if (node >= NN) return;
    int lane = threadIdx.x & 31;
    uint2 u = ((const uint2*)(h + (size_t)node * F2))[lane];
    float2 f0 = __half22float2(*(__half2*)&u.x);
    float2 f1 = __half22float2(*(__half2*)&u.y);
    int c = lane * 4;
    float h0 = fmaf(fmaxf(f0.x, 0.f), g_scale[c + 0], g_shift[c + 0]);
    float h1 = fmaf(fmaxf(f0.y, 0.f), g_scale[c + 1], g_shift[c + 1]);
    float h2 = fmaf(fmaxf(f1.x, 0.f), g_scale[c + 2], g_shift[c + 2]);
    float h3 = fmaf(fmaxf(f1.y, 0.f), g_scale[c + 3], g_shift[c + 3]);
#pragma unroll
    for (int o = 0; o < 10; ++o) {
        float4 w = ((const float4*)(Wl + o * F2))[lane];
        float p = h0 * w.x + h1 * w.y + h2 * w.z + h3 * w.w;
        p += __shfl_xor_sync(0xffffffffu, p, 16);
        p += __shfl_xor_sync(0xffffffffu, p, 8);
        p += __shfl_xor_sync(0xffffffffu, p, 4);
        p += __shfl_xor_sync(0xffffffffu, p, 2);
        p += __shfl_xor_sync(0xffffffffu, p, 1);
        if (lane == 0) out[node * 10 + o] = p + bl[o];
    }
}

// ---------------- launch ------------------------------------------------------
extern "C" void kernel_launch(void* const* d_in, const int* in_sizes, int n_in,
                              void* d_out, int out_size) {
    const float* x      = (const float*)d_in[0];
    const int*   ei     = (const int*)d_in[1];
    const float* ew     = (const float*)d_in[2];
    const float* W1     = (const float*)d_in[3];
    const float* b1     = (const float*)d_in[4];
    const float* W2     = (const float*)d_in[5];
    const float* b2     = (const float*)d_in[6];
    const float* gamma1 = (const float*)d_in[7];
    const float* beta1  = (const float*)d_in[8];
    const float* gamma2 = (const float*)d_in[9];
    const float* beta2  = (const float*)d_in[10];
    const float* Wlin   = (const float*)d_in[11];
    const float* blin   = (const float*)d_in[12];
    float* out = (float*)d_out;

    const int* row = ei;
    const int* col = ei + EE;

    float *deg, *out1, *stats;
    int *cnt;
    __half *TxA, *Ck, *out2;
    cudaGetSymbolAddress((void**)&deg,   g_deg);
    cudaGetSymbolAddress((void**)&cnt,   g_cnt);
    cudaGetSymbolAddress((void**)&TxA,   g_TxA);
    cudaGetSymbolAddress((void**)&out1,  g_out1);
    cudaGetSymbolAddress((void**)&Ck,    g_Ck);
    cudaGetSymbolAddress((void**)&out2,  g_out2);
    cudaGetSymbolAddress((void**)&stats, g_stats);

    const int EB = (EE + 255) / 256;
    const int SB = (NN * 32 + 255) / 256;   // warp-per-node grids

    // ---- CSR build ----
    cudaMemsetAsync(deg, 0, NPAD * sizeof(float));
    cudaMemsetAsync(cnt, 0, NPAD * sizeof(int));
    cudaMemsetAsync(stats, 0, 2 * F1 * sizeof(float));

    deg_cnt_kernel<<<EB, 256>>>(row, col, ew);
    scan_dis_kernel<<<1, 1024>>>();
    scatter_kernel<<<EB, 256>>>(row, col, ew);

    cvt_x_kernel<<<(NN * 32 + 255) / 256, 256>>>(x, TxA);

    // ---- layer 1: Chebyshev recursion at F=128 (fp16 features) ----
    __half* A0 = TxA;
    __half* A1 = TxA + (size_t)NPAD * F0;
    __half* A2 = TxA + (size_t)2 * NPAD * F0;
    __half* A3 = TxA + (size_t)3 * NPAD * F0;
    spmm_h<<<SB, 256>>>(A0, A1, nullptr, nullptr, 1.f);
    spmm_h<<<SB, 256>>>(A1, A2, A0, nullptr, 2.f);
    spmm_h<<<SB, 256>>>(A2, A3, A1, nullptr, 2.f);

    gemm1_f16<<<dim3(NPAD / 128, 2), 256>>>(TxA, W1, b1, out1);

    stats_f256<<<157, 256>>>(out1);
    scaleshift_kernel<<<1, 256>>>(gamma1, beta1, F1);
    cudaMemsetAsync(stats, 0, 2 * F1 * sizeof(float));

    // ---- layer 2: Horner form ----
    wcomb_kernel<<<(F1 * F2 + 255) / 256, 256>>>(W2);
    gemm2_f16<<<dim3(NPAD / 128, 4), 256>>>(out1, b2);

    __half* C0 = Ck;
    __half* C1 = Ck + (size_t)NPAD * F2;
    __half* C2 = Ck + (size_t)2 * NPAD * F2;
    __half* C3 = Ck + (size_t)3 * NPAD * F2;
    __half* t1 = TxA;
    __half* t2 = TxA + (size_t)NPAD * F0;
    spmm_h<<<SB, 256>>>(C3, t1, nullptr, C2, 1.f);
    spmm_h<<<SB, 256>>>(t1, t2, nullptr, C1, 1.f);
    spmm_h<<<SB, 256>>>(t2, out2, nullptr, C0, 1.f);

    stats_h128<<<157, 256>>>(out2);
    scaleshift_kernel<<<1, 128>>>(gamma2, beta2, F2);

    final_kernel<<<SB, 256>>>(out2, Wlin, blin, out);
}

// round 9
// speedup vs baseline: 1.3387x; 1.0778x over previous
#include <cuda_runtime.h>
#include <cuda_fp16.h>
#include <cstdint>

// Problem constants
#define NN   20000
#define EE   640000
#define F0   128
#define F1   256
#define F2   128
#define NPAD 20096   // 157 * 128

// ---------------- scratch (device globals, zero at module load) -------------
__device__ __align__(16) float  g_deg[NPAD];
__device__ __align__(16) int    g_cnt[NPAD];
__device__ __align__(16) int    g_pos[EE];
__device__ __align__(16) int    g_off[NN + 1];
__device__ __align__(16) int2   g_pack[EE];             // (src_row, w_norm) by dst
__device__ __align__(16) __half g_TxA[4 * NPAD * F0];   // fp16 feature stacks
__device__ __align__(16) __half g_out1[NPAD * F1];      // GEMM1 out (fp16, pre-BN)
__device__ __align__(16) __half g_Ck[4 * NPAD * F2];    // layer2 Horner coeffs
__device__ __align__(16) __half g_out2[NPAD * F2];
__device__ __align__(16) float  g_W2c[4 * F1 * F2];
__device__ __align__(16) float  g_stats[2 * F1];        // layer1 sum/sumsq
__device__ __align__(16) float  g_stats2[2 * F2];       // layer2 sum/sumsq

// ---------------- CSR build --------------------------------------------------
__global__ void deg_cnt_kernel(const int* __restrict__ row,
                               const int* __restrict__ col,
                               const float* __restrict__ ew) {
    int e = blockIdx.x * blockDim.x + threadIdx.x;
    if (e >= EE) return;
    int r = row[e], c = col[e];
    float w = (r == c) ? 0.f : ew[e];
    if (w != 0.f) atomicAdd(&g_deg[r], w);
    g_pos[e] = atomicAdd(&g_cnt[c], 1);
}

// fused: dis = rsqrt(deg); zero stats buffers; scan counts -> offsets
__global__ void scan_dis_kernel() {
    int tid = threadIdx.x;
    for (int i = tid; i < NN; i += 1024) {
        float d = g_deg[i];
        g_deg[i] = (d > 0.f) ? rsqrtf(d) : 0.f;
    }
    if (tid < 2 * F1) g_stats[tid] = 0.f;
    else if (tid < 2 * F1 + 2 * F2) g_stats2[tid - 2 * F1] = 0.f;

    const int PER = 20;
    int base = tid * PER;
    int v[PER];
    int s = 0;
#pragma unroll
    for (int j = 0; j < PER; j++) {
        int idx = base + j;
        int t = (idx < NN) ? g_cnt[idx] : 0;
        v[j] = t;
        s += t;
    }
    int lane = tid & 31, warp = tid >> 5;
    int p = s;
#pragma unroll
    for (int o = 1; o < 32; o <<= 1) {
        int t = __shfl_up_sync(0xffffffffu, p, o);
        if (lane >= o) p += t;
    }
    __shared__ int wsum[32];
    if (lane == 31) wsum[warp] = p;
    __syncthreads();
    if (warp == 0) {
        int q = wsum[lane];
#pragma unroll
        for (int o = 1; o < 32; o <<= 1) {
            int t = __shfl_up_sync(0xffffffffu, q, o);
            if (lane >= o) q += t;
        }
        wsum[lane] = q;
    }
    __syncthreads();
    int run = p - s + (warp ? wsum[warp - 1] : 0);
#pragma unroll
    for (int j = 0; j < PER; j++) {
        int idx = base + j;
        if (idx <= NN) g_off[idx] = run;
        run += v[j];
    }
}

__global__ void scatter_kernel(const int* __restrict__ row,
                               const int* __restrict__ col,
                               const float* __restrict__ ew) {
    int e = blockIdx.x * blockDim.x + threadIdx.x;
    if (e >= EE) return;
    int r = row[e], c = col[e];
    float w = (r == c) ? 0.f : ew[e];
    float wn = -g_deg[r] * w * g_deg[c];
    int2 p;
    p.x = r;
    p.y = __float_as_int(wn);
    g_pack[g_off[c] + g_pos[e]] = p;
}

// x (fp32) -> A0 (fp16)
__global__ void cvt_x_kernel(const float* __restrict__ x, __half* __restrict__ dst) {
    int i = blockIdx.x * blockDim.x + threadIdx.x;
    if (i >= NN * 32) return;
    float4 v = ((const float4*)x)[i];
    uint2 o;
    __half2 h0 = __floats2half2_rn(v.x, v.y);
    __half2 h1 = __floats2half2_rn(v.z, v.w);
    o.x = *(unsigned*)&h0;
    o.y = *(unsigned*)&h1;
    ((uint2*)dst)[i] = o;
}

// ---- gather SPMM (fp16, F=128): out = alpha*(L@in) - sub + add --------------
__device__ __forceinline__ void hfma4(float4& acc, float w, uint2 u) {
    float2 f0 = __half22float2(*(__half2*)&u.x);
    float2 f1 = __half22float2(*(__half2*)&u.y);
    acc.x = fmaf(w, f0.x, acc.x);
    acc.y = fmaf(w, f0.y, acc.y);
    acc.z = fmaf(w, f1.x, acc.z);
    acc.w = fmaf(w, f1.y, acc.w);
}

__global__ void spmm_h(const __half* __restrict__ in, __half* __restrict__ out,
                       const __half* __restrict__ sub,
                       const __half* __restrict__ add, float alpha) {
    int node = (blockIdx.x * blockDim.x + threadIdx.x) >> 5;
    if (node >= NN) return;
    int lane = threadIdx.x & 31;
    int beg = g_off[node], end = g_off[node + 1];

    const uint2* base = (const uint2*)in + lane;
    float4 acc0 = make_float4(0.f, 0.f, 0.f, 0.f);
    float4 acc1 = make_float4(0.f, 0.f, 0.f, 0.f);
    float4 acc2 = make_float4(0.f, 0.f, 0.f, 0.f);
    float4 acc3 = make_float4(0.f, 0.f, 0.f, 0.f);

    int i = beg;
    for (; i + 4 <= end; i += 4) {
        int2 p0 = g_pack[i + 0], p1 = g_pack[i + 1];
        int2 p2 = g_pack[i + 2], p3 = g_pack[i + 3];
        uint2 u0 = base[(size_t)p0.x * 32];
        uint2 u1 = base[(size_t)p1.x * 32];
        uint2 u2 = base[(size_t)p2.x * 32];
        uint2 u3 = base[(size_t)p3.x * 32];
        hfma4(acc0, __int_as_float(p0.y), u0);
        hfma4(acc1, __int_as_float(p1.y), u1);
        hfma4(acc2, __int_as_float(p2.y), u2);
        hfma4(acc3, __int_as_float(p3.y), u3);
    }
    for (; i < end; ++i) {
        int2 p0 = g_pack[i];
        uint2 u0 = base[(size_t)p0.x * 32];
        hfma4(acc0, __int_as_float(p0.y), u0);
    }
    float4 r;
    r.x = alpha * ((acc0.x + acc1.x) + (acc2.x + acc3.x));
    r.y = alpha * ((acc0.y + acc1.y) + (acc2.y + acc3.y));
    r.z = alpha * ((acc0.z + acc1.z) + (acc2.z + acc3.z));
    r.w = alpha * ((acc0.w + acc1.w) + (acc2.w + acc3.w));
    size_t oidx = (size_t)node * 32 + lane;
    if (add) {
        uint2 u = ((const uint2*)add)[oidx];
        float2 f0 = __half22float2(*(__half2*)&u.x);
        float2 f1 = __half22float2(*(__half2*)&u.y);
        r.x += f0.x; r.y += f0.y; r.z += f1.x; r.w += f1.y;
    }
    if (sub) {
        uint2 u = ((const uint2*)sub)[oidx];
        float2 f0 = __half22float2(*(__half2*)&u.x);
        float2 f1 = __half22float2(*(__half2*)&u.y);
        r.x -= f0.x; r.y -= f0.y; r.z -= f1.x; r.w -= f1.y;
    }
    uint2 o;
    __half2 h0 = __floats2half2_rn(r.x, r.y);
    __half2 h1 = __floats2half2_rn(r.z, r.w);
    o.x = *(unsigned*)&h0;
    o.y = *(unsigned*)&h1;
    ((uint2*)out)[oidx] = o;
}

// ---------------- fp16 tensor-core GEMMs -------------------------------------
#define PA 40    // A smem pitch (halves)
#define PB 136   // B smem pitch (halves)

// GEMM1: out1(h)[NPAD][256] = sum_chunk TxA_chunk @ W1_chunk + b1 ; fused BN1 stats
__global__ __launch_bounds__(256)
void gemm1_f16(const __half* __restrict__ A, const float* __restrict__ W,
               const float* __restrict__ bias, __half* __restrict__ C) {
    __shared__ __align__(16) __half As[128 * PA];
    __shared__ __align__(16) __half Bs[32 * PB];
    __shared__ float sS[128], sQ[128];

    const int tid = threadIdx.x;
    const int lane = tid & 31;
    const int wid = tid >> 5;
    const int warp_m = wid >> 2;
    const int warp_n = wid & 3;
    const int bm = blockIdx.x * 128;
    const int bn = blockIdx.y * 128;

    if (tid < 128) { sS[tid] = 0.f; sQ[tid] = 0.f; }

    float acc[4][4][4];
#pragma unroll
    for (int i = 0; i < 4; i++)
#pragma unroll
        for (int j = 0; j < 4; j++)
#pragma unroll
            for (int q = 0; q < 4; q++) acc[i][j][q] = 0.f;

    const unsigned asBase = (unsigned)__cvta_generic_to_shared(
        &As[(warp_m * 64 + (lane & 15)) * PA + (lane >> 4) * 8]);
    const int b_k = ((lane >> 3) & 1) * 8 + (lane & 7);
    const int b_n = (lane >> 4) * 8;

#pragma unroll 1
    for (int chunk = 0; chunk < 4; ++chunk) {
        const __half* Ab = A + (size_t)chunk * NPAD * F0;
        const float*  Wb = W + (size_t)chunk * F0 * F1;
#pragma unroll 1
        for (int k0 = 0; k0 < F0; k0 += 32) {
            {
                int m = tid >> 2;
                int kq = (tid & 3) * 8;
#pragma unroll
                for (int p = 0; p < 2; ++p) {
                    int rowm = m + p * 64;
                    uint4 v = *(const uint4*)(Ab + (size_t)(bm + rowm) * F0 + k0 + kq);
                    *(uint4*)&As[rowm * PA + kq] = v;
                }
            }
            {
                int kk = tid >> 5;
                int n4 = (tid & 31) * 4;
#pragma unroll
                for (int p = 0; p < 4; ++p) {
                    int kr = kk + p * 8;
                    float4 v = *(const float4*)(Wb + (size_t)(k0 + kr) * F1 + bn + n4);
                    __half2 h0 = __floats2half2_rn(v.x, v.y);
                    __half2 h1 = __floats2half2_rn(v.z, v.w);
                    uint2 o;
                    o.x = *(unsigned*)&h0;
                    o.y = *(unsigned*)&h1;
                    *(uint2*)&Bs[kr * PB + n4] = o;
                }
            }
            __syncthreads();
#pragma unroll
            for (int ks = 0; ks < 2; ++ks) {
                unsigned a[4][4];
#pragma unroll
                for (int ms = 0; ms < 4; ++ms) {
                    unsigned addr = asBase + ms * (16 * PA * 2) + ks * 32;
                    asm volatile(
                        "ldmatrix.sync.aligned.m8n8.x4.shared.b16 {%0,%1,%2,%3}, [%4];"
                        : "=r"(a[ms][0]), "=r"(a[ms][1]), "=r"(a[ms][2]), "=r"(a[ms][3])
                        : "r"(addr));
                }
                unsigned b[4][2];
#pragma unroll
                for (int nsp = 0; nsp < 2; ++nsp) {
                    int ncol = warp_n * 32 + nsp * 16 + b_n;
                    unsigned baddr = (unsigned)__cvta_generic_to_shared(
                        &Bs[(ks * 16 + b_k) * PB + ncol]);
                    asm volatile(
                        "ldmatrix.sync.aligned.m8n8.x4.trans.shared.b16 {%0,%1,%2,%3}, [%4];"
                        : "=r"(b[2 * nsp][0]), "=r"(b[2 * nsp][1]),
                          "=r"(b[2 * nsp + 1][0]), "=r"(b[2 * nsp + 1][1])
                        : "r"(baddr));
                }
#pragma unroll
                for (int ms = 0; ms < 4; ++ms)
#pragma unroll
                    for (int ns = 0; ns < 4; ++ns) {
                        asm volatile(
                            "mma.sync.aligned.m16n8k16.row.col.f32.f16.f16.f32 "
                            "{%0,%1,%2,%3}, {%4,%5,%6,%7}, {%8,%9}, {%0,%1,%2,%3};"
                            : "+f"(acc[ms][ns][0]), "+f"(acc[ms][ns][1]),
                              "+f"(acc[ms][ns][2]), "+f"(acc[ms][ns][3])
                            : "r"(a[ms][0]), "r"(a[ms][1]), "r"(a[ms][2]), "r"(a[ms][3]),
                              "r"(b[ns][0]), "r"(b[ns][1]));
                    }
            }
            __syncthreads();
        }
    }

    // epilogue: store fp16 + accumulate BN stats (relu) for rows < NN
    float s[4][2], q[4][2];
#pragma unroll
    for (int ns = 0; ns < 4; ++ns) { s[ns][0] = s[ns][1] = q[ns][0] = q[ns][1] = 0.f; }
#pragma unroll
    for (int ms = 0; ms < 4; ++ms) {
        int r0 = bm + warp_m * 64 + ms * 16 + (lane >> 2);
        bool ok0 = r0 < NN, ok1 = (r0 + 8) < NN;
#pragma unroll
        for (int ns = 0; ns < 4; ++ns) {
            int cc = bn + warp_n * 32 + ns * 8 + 2 * (lane & 3);
            float v0 = acc[ms][ns][0] + bias[cc + 0];
            float v1 = acc[ms][ns][1] + bias[cc + 1];
            float v2 = acc[ms][ns][2] + bias[cc + 0];
            float v3 = acc[ms][ns][3] + bias[cc + 1];
            __half2 h0 = __floats2half2_rn(v0, v1);
            __half2 h1 = __floats2half2_rn(v2, v3);
            *(__half2*)&C[(size_t)r0 * F1 + cc] = h0;
            *(__half2*)&C[(size_t)(r0 + 8) * F1 + cc] = h1;
            float a0 = ok0 ? fmaxf(v0, 0.f) : 0.f;
            float a1 = ok0 ? fmaxf(v1, 0.f) : 0.f;
            float a2 = ok1 ? fmaxf(v2, 0.f) : 0.f;
            float a3 = ok1 ? fmaxf(v3, 0.f) : 0.f;
            s[ns][0] += a0 + a2;
            s[ns][1] += a1 + a3;
            q[ns][0] += a0 * a0 + a2 * a2;
            q[ns][1] += a1 * a1 + a3 * a3;
        }
    }
#pragma unroll
    for (int ns = 0; ns < 4; ++ns)
#pragma unroll
        for (int par = 0; par < 2; ++par) {
            float sv = s[ns][par], qv = q[ns][par];
            sv += __shfl_xor_sync(0xffffffffu, sv, 4);
            sv += __shfl_xor_sync(0xffffffffu, sv, 8);
            sv += __shfl_xor_sync(0xffffffffu, sv, 16);
            qv += __shfl_xor_sync(0xffffffffu, qv, 4);
            qv += __shfl_xor_sync(0xffffffffu, qv, 8);
            qv += __shfl_xor_sync(0xffffffffu, qv, 16);
            if (lane < 4) {
                int colL = warp_n * 32 + ns * 8 + 2 * lane + par;
                atomicAdd(&sS[colL], sv);
                atomicAdd(&sQ[colL], qv);
            }
        }
    __syncthreads();
    if (tid < 128) {
        atomicAdd(&g_stats[bn + tid], sS[tid]);
        atomicAdd(&g_stats[F1 + bn + tid], sQ[tid]);
    }
}

// weight precombine for layer-2 Horner form
__global__ void wcomb_kernel(const float* __restrict__ W2) {
    int i = blockIdx.x * blockDim.x + threadIdx.x;
    const int SZ = F1 * F2;
    if (i >= SZ) return;
    float w0 = W2[i], w1 = W2[SZ + i], w2 = W2[2 * SZ + i], w3 = W2[3 * SZ + i];
    g_W2c[i]          = w0 - w2;
    g_W2c[SZ + i]     = w1 - 3.f * w3;
    g_W2c[2 * SZ + i] = 2.f * w2;
    g_W2c[3 * SZ + i] = 4.f * w3;
}

// GEMM2: C_k(h) = BNrelu(out1(h)) @ W2c_k (+ b2 for k=0); scale/shift from g_stats
__global__ __launch_bounds__(256)
void gemm2_f16(const __half* __restrict__ A, const float* __restrict__ bias,
               const float* __restrict__ gamma, const float* __restrict__ beta) {
    __shared__ __align__(16) __half As[128 * PA];
    __shared__ __align__(16) __half Bs[32 * PB];
    __shared__ float sSc[F1], sSh[F1];

    const int tid = threadIdx.x;
    const int lane = tid & 31;
    const int wid = tid >> 5;
    const int warp_m = wid >> 2;
    const int warp_n = wid & 3;
    const int bm = blockIdx.x * 128;
    const int kblk = blockIdx.y;
    const float* Wb = g_W2c + (size_t)kblk * F1 * F2;
    __half* C = g_Ck + (size_t)kblk * NPAD * F2;

    {
        float m = g_stats[tid] * (1.f / NN);
        float v = g_stats[F1 + tid] * (1.f / NN) - m * m;
        float inv = rsqrtf(v + 1e-5f);
        float sc = gamma[tid] * inv;
        sSc[tid] = sc;
        sSh[tid] = beta[tid] - m * sc;
    }
    __syncthreads();

    float acc[4][4][4];
#pragma unroll
    for (int i = 0; i < 4; i++)
#pragma unroll
        for (int j = 0; j < 4; j++)
#pragma unroll
            for (int q = 0; q < 4; q++) acc[i][j][q] = 0.f;

    const unsigned asBase = (unsigned)__cvta_generic_to_shared(
        &As[(warp_m * 64 + (lane & 15)) * PA + (lane >> 4) * 8]);
    const int b_k = ((lane >> 3) & 1) * 8 + (lane & 7);
    const int b_n = (lane >> 4) * 8;

#pragma unroll 1
    for (int k0 = 0; k0 < F1; k0 += 32) {
        {
            int m = tid >> 2;
            int kq = (tid & 3) * 8;
            float sc[8], sh[8];
#pragma unroll
            for (int j = 0; j < 8; ++j) {
                sc[j] = sSc[k0 + kq + j];
                sh[j] = sSh[k0 + kq + j];
            }
#pragma unroll
            for (int p = 0; p < 2; ++p) {
                int rowm = m + p * 64;
                uint4 u = *(const uint4*)(A + (size_t)(bm + rowm) * F1 + k0 + kq);
                float2 f0 = __half22float2(*(__half2*)&u.x);
                float2 f1 = __half22float2(*(__half2*)&u.y);
                float2 f2 = __half22float2(*(__half2*)&u.z);
                float2 f3 = __half22float2(*(__half2*)&u.w);
                float w0 = fmaf(fmaxf(f0.x, 0.f), sc[0], sh[0]);
                float w1 = fmaf(fmaxf(f0.y, 0.f), sc[1], sh[1]);
                float w2 = fmaf(fmaxf(f1.x, 0.f), sc[2], sh[2]);
                float w3 = fmaf(fmaxf(f1.y, 0.f), sc[3], sh[3]);
                float w4 = fmaf(fmaxf(f2.x, 0.f), sc[4], sh[4]);
                float w5 = fmaf(fmaxf(f2.y, 0.f), sc[5], sh[5]);
                float w6 = fmaf(fmaxf(f3.x, 0.f), sc[6], sh[6]);
                float w7 = fmaf(fmaxf(f3.y, 0.f), sc[7], sh[7]);
                __half2 h0 = __floats2half2_rn(w0, w1);
                __half2 h1 = __floats2half2_rn(w2, w3);
                __half2 h2 = __floats2half2_rn(w4, w5);
                __half2 h3 = __floats2half2_rn(w6, w7);
                uint4 o;
                o.x = *(unsigned*)&h0; o.y = *(unsigned*)&h1;
                o.z = *(unsigned*)&h2; o.w = *(unsigned*)&h3;
                *(uint4*)&As[rowm * PA + kq] = o;
            }
        }
        {
            int kk = tid >> 5;
            int n4 = (tid & 31) * 4;
#pragma unroll
            for (int p = 0; p < 4; ++p) {
                int kr = kk + p * 8;
                float4 v = *(const float4*)(Wb + (size_t)(k0 + kr) * F2 + n4);
                __half2 h0 = __floats2half2_rn(v.x, v.y);
                __half2 h1 = __floats2half2_rn(v.z, v.w);
                uint2 o;
                o.x = *(unsigned*)&h0;
                o.y = *(unsigned*)&h1;
                *(uint2*)&Bs[kr * PB + n4] = o;
            }
        }
        __syncthreads();
#pragma unroll
        for (int ks = 0; ks < 2; ++ks) {
            unsigned a[4][4];
#pragma unroll
            for (int ms = 0; ms < 4; ++ms) {
                unsigned addr = asBase + ms * (16 * PA * 2) + ks * 32;
                asm volatile(
                    "ldmatrix.sync.aligned.m8n8.x4.shared.b16 {%0,%1,%2,%3}, [%4];"
                    : "=r"(a[ms][0]), "=r"(a[ms][1]), "=r"(a[ms][2]), "=r"(a[ms][3])
                    : "r"(addr));
            }
            unsigned b[4][2];
#pragma unroll
            for (int nsp = 0; nsp < 2; ++nsp) {
                int ncol = warp_n * 32 + nsp * 16 + b_n;
                unsigned baddr = (unsigned)__cvta_generic_to_shared(
                    &Bs[(ks * 16 + b_k) * PB + ncol]);
                asm volatile(
                    "ldmatrix.sync.aligned.m8n8.x4.trans.shared.b16 {%0,%1,%2,%3}, [%4];"
                    : "=r"(b[2 * nsp][0]), "=r"(b[2 * nsp][1]),
                      "=r"(b[2 * nsp + 1][0]), "=r"(b[2 * nsp + 1][1])
                    : "r"(baddr));
            }
#pragma unroll
            for (int ms = 0; ms < 4; ++ms)
#pragma unroll
                for (int ns = 0; ns < 4; ++ns) {
                    asm volatile(
                        "mma.sync.aligned.m16n8k16.row.col.f32.f16.f16.f32 "
                        "{%0,%1,%2,%3}, {%4,%5,%6,%7}, {%8,%9}, {%0,%1,%2,%3};"
                        : "+f"(acc[ms][ns][0]), "+f"(acc[ms][ns][1]),
                          "+f"(acc[ms][ns][2]), "+f"(acc[ms][ns][3])
                        : "r"(a[ms][0]), "r"(a[ms][1]), "r"(a[ms][2]), "r"(a[ms][3]),
                          "r"(b[ns][0]), "r"(b[ns][1]));
                }
        }
        __syncthreads();
    }
    bool addb = (kblk == 0);
#pragma unroll
    for (int ms = 0; ms < 4; ++ms) {
        int r0 = bm + warp_m * 64 + ms * 16 + (lane >> 2);
#pragma unroll
        for (int ns = 0; ns < 4; ++ns) {
            int cc = warp_n * 32 + ns * 8 + 2 * (lane & 3);
            float bx = addb ? bias[cc + 0] : 0.f;
            float by = addb ? bias[cc + 1] : 0.f;
            __half2 h0 = __floats2half2_rn(acc[ms][ns][0] + bx, acc[ms][ns][1] + by);
            __half2 h1 = __floats2half2_rn(acc[ms][ns][2] + bx, acc[ms][ns][3] + by);
            *(__half2*)&C[(size_t)r0 * F2 + cc] = h0;
            *(__half2*)&C[(size_t)(r0 + 8) * F2 + cc] = h1;
        }
    }
}

// ---------------- BN2 stats ---------------------------------------------------
__global__ void stats_h128(const __half* __restrict__ X) {
    int col = threadIdx.x & 127;
    int ro = threadIdx.x >> 7;
    int r0 = blockIdx.x * 128 + ro;
    int rend = blockIdx.x * 128 + 128;
    if (rend > NN) rend = NN;
    float s = 0.f, s2 = 0.f;
    for (int r = r0; r < rend; r += 2) {
        float v = __half2float(X[(size_t)r * F2 + col]);
        v = v > 0.f ? v : 0.f;
        s += v;
        s2 = fmaf(v, v, s2);
    }
    atomicAdd(&g_stats2[col], s);
    atomicAdd(&g_stats2[F2 + col], s2);
}

// ---- final: out = BNrelu(out2(h)) @ Wlin^T + blin; scale/shift from g_stats2 -
__global__ void final_kernel(const __half* __restrict__ h, const float* __restrict__ Wl,
                             const float* __restrict__ bl,
                             const float* __restrict__ gamma, const float* __restrict__ beta,
                             float* __restrict__ out) {
    __shared__ float fSc[F2], fSh[F2];
    int tid = threadIdx.x;
    if (tid < F2) {
        float m = g_stats2[tid] * (1.f / NN);
        float v = g_stats2[F2 + tid] * (1.f / NN) - m * m;
        float inv = rsqrtf(v + 1e-5f);
        float sc = gamma[tid] * inv;
        fSc[tid] = sc;
        fSh[tid] = beta[tid] - m * sc;
    }
    __syncthreads();

    int node = (blockIdx.x * blockDim.x + tid) >> 5;
    if (node >= NN) return;
    int lane = tid & 31;
    uint2 u = ((const uint2*)(h + (size_t)node * F2))[lane];
    float2 f0 = __half22float2(*(__half2*)&u.x);
    float2 f1 = __half22float2(*(__half2*)&u.y);
    int c = lane * 4;
    float h0 = fmaf(fmaxf(f0.x, 0.f), fSc[c + 0], fSh[c + 0]);
    float h1 = fmaf(fmaxf(f0.y, 0.f), fSc[c + 1], fSh[c + 1]);
    float h2 = fmaf(fmaxf(f1.x, 0.f), fSc[c + 2], fSh[c + 2]);
    float h3 = fmaf(fmaxf(f1.y, 0.f), fSc[c + 3], fSh[c + 3]);
#pragma unroll
    for (int o = 0; o < 10; ++o) {
        float4 w = ((const float4*)(Wl + o * F2))[lane];
        float p = h0 * w.x + h1 * w.y + h2 * w.z + h3 * w.w;
        p += __shfl_xor_sync(0xffffffffu, p, 16);
        p += __shfl_xor_sync(0xffffffffu, p, 8);
        p += __shfl_xor_sync(0xffffffffu, p, 4);
        p += __shfl_xor_sync(0xffffffffu, p, 2);
        p += __shfl_xor_sync(0xffffffffu, p, 1);
        if (lane == 0) out[node * 10 + o] = p + bl[o];
    }
}

// ---------------- launch ------------------------------------------------------
extern "C" void kernel_launch(void* const* d_in, const int* in_sizes, int n_in,
                              void* d_out, int out_size) {
    const float* x      = (const float*)d_in[0];
    const int*   ei     = (const int*)d_in[1];
    const float* ew     = (const float*)d_in[2];
    const float* W1     = (const float*)d_in[3];
    const float* b1     = (const float*)d_in[4];
    const float* W2     = (const float*)d_in[5];
    const float* b2     = (const float*)d_in[6];
    const float* gamma1 = (const float*)d_in[7];
    const float* beta1  = (const float*)d_in[8];
    const float* gamma2 = (const float*)d_in[9];
    const float* beta2  = (const float*)d_in[10];
    const float* Wlin   = (const float*)d_in[11];
    const float* blin   = (const float*)d_in[12];
    float* out = (float*)d_out;

    const int* row = ei;
    const int* col = ei + EE;

    float *deg;
    int *cnt;
    __half *TxA, *out1, *Ck, *out2;
    cudaGetSymbolAddress((void**)&deg,  g_deg);
    cudaGetSymbolAddress((void**)&cnt,  g_cnt);
    cudaGetSymbolAddress((void**)&TxA,  g_TxA);
    cudaGetSymbolAddress((void**)&out1, g_out1);
    cudaGetSymbolAddress((void**)&Ck,   g_Ck);
    cudaGetSymbolAddress((void**)&out2, g_out2);

    const int EB = (EE + 255) / 256;
    const int SB = (NN * 32 + 255) / 256;

    // ---- CSR build ----
    cudaMemsetAsync(deg, 0, NPAD * sizeof(float));
    cudaMemsetAsync(cnt, 0, NPAD * sizeof(int));

    deg_cnt_kernel<<<EB, 256>>>(row, col, ew);
    scan_dis_kernel<<<1, 1024>>>();
    scatter_kernel<<<EB, 256>>>(row, col, ew);

    cvt_x_kernel<<<(NN * 32 + 255) / 256, 256>>>(x, TxA);

    // ---- layer 1: Chebyshev recursion at F=128 (fp16 features) ----
    __half* A0 = TxA;
    __half* A1 = TxA + (size_t)NPAD * F0;
    __half* A2 = TxA + (size_t)2 * NPAD * F0;
    __half* A3 = TxA + (size_t)3 * NPAD * F0;
    spmm_h<<<SB, 256>>>(A0, A1, nullptr, nullptr, 1.f);
    spmm_h<<<SB, 256>>>(A1, A2, A0, nullptr, 2.f);
    spmm_h<<<SB, 256>>>(A2, A3, A1, nullptr, 2.f);

    gemm1_f16<<<dim3(NPAD / 128, 2), 256>>>(TxA, W1, b1, out1);

    // ---- layer 2: Horner form ----
    wcomb_kernel<<<(F1 * F2 + 255) / 256, 256>>>(W2);
    gemm2_f16<<<dim3(NPAD / 128, 4), 256>>>(out1, b2, gamma1, beta1);

    __half* C0 = Ck;
    __half* C1 = Ck + (size_t)NPAD * F2;
    __half* C2 = Ck + (size_t)2 * NPAD * F2;
    __half* C3 = Ck + (size_t)3 * NPAD * F2;
    __half* t1 = TxA;
    __half* t2 = TxA + (size_t)NPAD * F0;
    spmm_h<<<SB, 256>>>(C3, t1, nullptr, C2, 1.f);
    spmm_h<<<SB, 256>>>(t1, t2, nullptr, C1, 1.f);
    spmm_h<<<SB, 256>>>(t2, out2, nullptr, C0, 1.f);

    stats_h128<<<157, 256>>>(out2);

    final_kernel<<<SB, 256>>>(out2, Wlin, blin, gamma2, beta2, out);
}

// round 10
// speedup vs baseline: 1.3874x; 1.0364x over previous
#include <cuda_runtime.h>
#include <cuda_fp16.h>
#include <cstdint>

// Problem constants
#define NN   20000
#define EE   640000
#define F0   128
#define F1   256
#define F2   128
#define NPAD 20096   // 157 * 128

// ---------------- scratch (device globals, zero at module load) -------------
__device__ __align__(16) float  g_deg[NPAD];
__device__ __align__(16) int    g_cnt[NPAD];
__device__ __align__(16) int    g_pos[EE];
__device__ __align__(16) int    g_off[NN + 1];
__device__ __align__(16) int2   g_pack[EE];             // (src_row, w_norm) by dst
__device__ __align__(16) __half g_TxA[4 * NPAD * F0];   // fp16 feature stacks
__device__ __align__(16) __half g_out1[NPAD * F1];      // relu(GEMM1 out), fp16
__device__ __align__(16) __half g_Ck[4 * NPAD * F2];    // layer2 Horner coeffs
__device__ __align__(16) __half g_out2[NPAD * F2];
__device__ __align__(16) __half g_W1h[4 * F0 * F1];     // W1 in fp16
__device__ __align__(16) __half g_W2h[4 * F1 * F2];     // sc ⊙ W2c (fp16)
__device__ __align__(16) float  g_bias2[4 * F2];        // sh @ W2c_k (+ b2)
__device__ __align__(16) float  g_Wlh[10 * F2];         // sc2 ⊙ Wlin
__device__ __align__(16) float  g_biasl[16];            // blin + sh2 @ Wlin^T
__device__ __align__(16) float  g_stats[2 * F1];        // layer1 sum/sumsq
__device__ __align__(16) float  g_stats2[2 * F2];       // layer2 sum/sumsq

// ---------------- CSR build --------------------------------------------------
__global__ void deg_cnt_kernel(const int* __restrict__ row,
                               const int* __restrict__ col,
                               const float* __restrict__ ew) {
    int e = blockIdx.x * blockDim.x + threadIdx.x;
    if (e >= EE) return;
    int r = row[e], c = col[e];
    float w = (r == c) ? 0.f : ew[e];
    if (w != 0.f) atomicAdd(&g_deg[r], w);
    g_pos[e] = atomicAdd(&g_cnt[c], 1);
}

// fused: dis = rsqrt(deg); zero stats/bias buffers; scan counts -> offsets
__global__ void scan_dis_kernel() {
    int tid = threadIdx.x;
    for (int i = tid; i < NN; i += 1024) {
        float d = g_deg[i];
        g_deg[i] = (d > 0.f) ? rsqrtf(d) : 0.f;
    }
    if (tid < 2 * F1) g_stats[tid] = 0.f;
    if (tid < 2 * F2) g_stats2[tid] = 0.f;
    if (tid < 4 * F2) g_bias2[tid] = 0.f;
    if (tid < 16) g_biasl[tid] = 0.f;

    const int PER = 20;
    int base = tid * PER;
    int v[PER];
    int s = 0;
#pragma unroll
    for (int j = 0; j < PER; j++) {
        int idx = base + j;
        int t = (idx < NN) ? g_cnt[idx] : 0;
        v[j] = t;
        s += t;
    }
    int lane = tid & 31, warp = tid >> 5;
    int p = s;
#pragma unroll
    for (int o = 1; o < 32; o <<= 1) {
        int t = __shfl_up_sync(0xffffffffu, p, o);
        if (lane >= o) p += t;
    }
    __shared__ int wsum[32];
    if (lane == 31) wsum[warp] = p;
    __syncthreads();
    if (warp == 0) {
        int q = wsum[lane];
#pragma unroll
        for (int o = 1; o < 32; o <<= 1) {
            int t = __shfl_up_sync(0xffffffffu, q, o);
            if (lane >= o) q += t;
        }
        wsum[lane] = q;
    }
    __syncthreads();
    int run = p - s + (warp ? wsum[warp - 1] : 0);
#pragma unroll
    for (int j = 0; j < PER; j++) {
        int idx = base + j;
        if (idx <= NN) g_off[idx] = run;
        run += v[j];
    }
}

__global__ void scatter_kernel(const int* __restrict__ row,
                               const int* __restrict__ col,
                               const float* __restrict__ ew) {
    int e = blockIdx.x * blockDim.x + threadIdx.x;
    if (e >= EE) return;
    int r = row[e], c = col[e];
    float w = (r == c) ? 0.f : ew[e];
    float wn = -g_deg[r] * w * g_deg[c];
    int2 p;
    p.x = r;
    p.y = __float_as_int(wn);
    g_pack[g_off[c] + g_pos[e]] = p;
}

// x (fp32) -> A0 (fp16)
__global__ void cvt_x_kernel(const float* __restrict__ x, __half* __restrict__ dst) {
    int i = blockIdx.x * blockDim.x + threadIdx.x;
    if (i >= NN * 32) return;
    float4 v = ((const float4*)x)[i];
    uint2 o;
    __half2 h0 = __floats2half2_rn(v.x, v.y);
    __half2 h1 = __floats2half2_rn(v.z, v.w);
    o.x = *(unsigned*)&h0;
    o.y = *(unsigned*)&h1;
    ((uint2*)dst)[i] = o;
}

// W1 fp32 -> fp16
__global__ void w1cvt_kernel(const float* __restrict__ W1) {
    int i = blockIdx.x * blockDim.x + threadIdx.x;
    if (i >= 4 * F0 * F1 / 4) return;
    float4 v = ((const float4*)W1)[i];
    uint2 o;
    __half2 h0 = __floats2half2_rn(v.x, v.y);
    __half2 h1 = __floats2half2_rn(v.z, v.w);
    o.x = *(unsigned*)&h0;
    o.y = *(unsigned*)&h1;
    ((uint2*)g_W1h)[i] = o;
}

// ---- gather SPMM (fp16, F=128): out = alpha*(L@in) - sub + add --------------
__device__ __forceinline__ void hfma4(float4& acc, float w, uint2 u) {
    float2 f0 = __half22float2(*(__half2*)&u.x);
    float2 f1 = __half22float2(*(__half2*)&u.y);
    acc.x = fmaf(w, f0.x, acc.x);
    acc.y = fmaf(w, f0.y, acc.y);
    acc.z = fmaf(w, f1.x, acc.z);
    acc.w = fmaf(w, f1.y, acc.w);
}

__global__ void spmm_h(const __half* __restrict__ in, __half* __restrict__ out,
                       const __half* __restrict__ sub,
                       const __half* __restrict__ add, float alpha) {
    int node = (blockIdx.x * blockDim.x + threadIdx.x) >> 5;
    if (node >= NN) return;
    int lane = threadIdx.x & 31;
    int beg = g_off[node], end = g_off[node + 1];

    const uint2* base = (const uint2*)in + lane;
    float4 acc0 = make_float4(0.f, 0.f, 0.f, 0.f);
    float4 acc1 = make_float4(0.f, 0.f, 0.f, 0.f);
    float4 acc2 = make_float4(0.f, 0.f, 0.f, 0.f);
    float4 acc3 = make_float4(0.f, 0.f, 0.f, 0.f);

    int i = beg;
    for (; i + 4 <= end; i += 4) {
        int2 p0 = g_pack[i + 0], p1 = g_pack[i + 1];
        int2 p2 = g_pack[i + 2], p3 = g_pack[i + 3];
        uint2 u0 = base[(size_t)p0.x * 32];
        uint2 u1 = base[(size_t)p1.x * 32];
        uint2 u2 = base[(size_t)p2.x * 32];
        uint2 u3 = base[(size_t)p3.x * 32];
        hfma4(acc0, __int_as_float(p0.y), u0);
        hfma4(acc1, __int_as_float(p1.y), u1);
        hfma4(acc2, __int_as_float(p2.y), u2);
        hfma4(acc3, __int_as_float(p3.y), u3);
    }
    for (; i < end; ++i) {
        int2 p0 = g_pack[i];
        uint2 u0 = base[(size_t)p0.x * 32];
        hfma4(acc0, __int_as_float(p0.y), u0);
    }
    float4 r;
    r.x = alpha * ((acc0.x + acc1.x) + (acc2.x + acc3.x));
    r.y = alpha * ((acc0.y + acc1.y) + (acc2.y + acc3.y));
    r.z = alpha * ((acc0.z + acc1.z) + (acc2.z + acc3.z));
    r.w = alpha * ((acc0.w + acc1.w) + (acc2.w + acc3.w));
    size_t oidx = (size_t)node * 32 + lane;
    if (add) {
        uint2 u = ((const uint2*)add)[oidx];
        float2 f0 = __half22float2(*(__half2*)&u.x);
        float2 f1 = __half22float2(*(__half2*)&u.y);
        r.x += f0.x; r.y += f0.y; r.z += f1.x; r.w += f1.y;
    }
    if (sub) {
        uint2 u = ((const uint2*)sub)[oidx];
        float2 f0 = __half22float2(*(__half2*)&u.x);
        float2 f1 = __half22float2(*(__half2*)&u.y);
        r.x -= f0.x; r.y -= f0.y; r.z -= f1.x; r.w -= f1.y;
    }
    uint2 o;
    __half2 h0 = __floats2half2_rn(r.x, r.y);
    __half2 h1 = __floats2half2_rn(r.z, r.w);
    o.x = *(unsigned*)&h0;
    o.y = *(unsigned*)&h1;
    ((uint2*)out)[oidx] = o;
}

// ---------------- fp16 tensor-core GEMMs, cp.async double-buffered -----------
#define PA 40      // A smem pitch in halves (80B, 16B-aligned)
#define PB 136     // B smem pitch in halves (272B)
#define ASTG (128 * PA)
#define BSTG (32 * PB)

__device__ __forceinline__ void cp16(unsigned sdst, const void* gsrc) {
    asm volatile("cp.async.cg.shared.global [%0], [%1], 16;" :: "r"(sdst), "l"(gsrc));
}

// GEMM1: out1(h) = relu( sum_chunk TxA_chunk @ W1h_chunk + b1 ) ; fused BN1 stats
__global__ __launch_bounds__(256)
void gemm1_f16(const __half* __restrict__ A, const float* __restrict__ bias,
               __half* __restrict__ C) {
    __shared__ __align__(16) __half As[2 * ASTG];
    __shared__ __align__(16) __half Bs[2 * BSTG];
    __shared__ float sS[128], sQ[128];

    const int tid = threadIdx.x;
    const int lane = tid & 31;
    const int wid = tid >> 5;
    const int warp_m = wid >> 2;
    const int warp_n = wid & 3;
    const int bm = blockIdx.x * 128;
    const int bn = blockIdx.y * 128;
    const int NIT = 16;   // 4 chunks * (128/32)

    if (tid < 128) { sS[tid] = 0.f; sQ[tid] = 0.f; }

    float acc[4][4][4];
#pragma unroll
    for (int i = 0; i < 4; i++)
#pragma unroll
        for (int j = 0; j < 4; j++)
#pragma unroll
            for (int q = 0; q < 4; q++) acc[i][j][q] = 0.f;

    const unsigned asBase0 = (unsigned)__cvta_generic_to_shared(As);
    const unsigned bsBase0 = (unsigned)__cvta_generic_to_shared(Bs);
    const unsigned asFrag = asBase0 +
        ((warp_m * 64 + (lane & 15)) * PA + (lane >> 4) * 8) * 2;
    const int b_k = ((lane >> 3) & 1) * 8 + (lane & 7);
    const int b_n = (lane >> 4) * 8;

    auto load_tiles = [&](int st, int it) {
        int chunk = it >> 2;
        int k0 = (it & 3) * 32;
        const __half* Ab = A + (size_t)chunk * NPAD * F0 + (size_t)bm * F0 + k0;
        const __half* Wb = g_W1h + (size_t)chunk * F0 * F1 + (size_t)k0 * F1 + bn;
        unsigned sA = asBase0 + st * ASTG * 2;
        unsigned sB = bsBase0 + st * BSTG * 2;
#pragma unroll
        for (int p = 0; p < 2; ++p) {
            int idx = p * 256 + tid;
            int row = idx >> 2, ch = (idx & 3) * 8;
            cp16(sA + (row * PA + ch) * 2, Ab + (size_t)row * F0 + ch);
            int kr = idx >> 4, bc = (idx & 15) * 8;
            cp16(sB + (kr * PB + bc) * 2, Wb + (size_t)kr * F1 + bc);
        }
        asm volatile("cp.async.commit_group;");
    };

    load_tiles(0, 0);
    int st = 0;
#pragma unroll 1
    for (int it = 0; it < NIT; ++it) {
        if (it + 1 < NIT) {
            load_tiles(st ^ 1, it + 1);
            asm volatile("cp.async.wait_group 1;");
        } else {
            asm volatile("cp.async.wait_group 0;");
        }
        __syncthreads();
#pragma unroll
        for (int ks = 0; ks < 2; ++ks) {
            unsigned a[4][4];
#pragma unroll
            for (int ms = 0; ms < 4; ++ms) {
                unsigned addr = asFrag + st * ASTG * 2 + ms * (16 * PA * 2) + ks * 32;
                asm volatile(
                    "ldmatrix.sync.aligned.m8n8.x4.shared.b16 {%0,%1,%2,%3}, [%4];"
                    : "=r"(a[ms][0]), "=r"(a[ms][1]), "=r"(a[ms][2]), "=r"(a[ms][3])
                    : "r"(addr));
            }
            unsigned b[4][2];
#pragma unroll
            for (int nsp = 0; nsp < 2; ++nsp) {
                int ncol = warp_n * 32 + nsp * 16 + b_n;
                unsigned baddr = bsBase0 + st * BSTG * 2 +
                                 ((ks * 16 + b_k) * PB + ncol) * 2;
                asm volatile(
                    "ldmatrix.sync.aligned.m8n8.x4.trans.shared.b16 {%0,%1,%2,%3}, [%4];"
                    : "=r"(b[2 * nsp][0]), "=r"(b[2 * nsp][1]),
                      "=r"(b[2 * nsp + 1][0]), "=r"(b[2 * nsp + 1][1])
                    : "r"(baddr));
            }
#pragma unroll
            for (int ms = 0; ms < 4; ++ms)
#pragma unroll
                for (int ns = 0; ns < 4; ++ns) {
                    asm volatile(
                        "mma.sync.aligned.m16n8k16.row.col.f32.f16.f16.f32 "
                        "{%0,%1,%2,%3}, {%4,%5,%6,%7}, {%8,%9}, {%0,%1,%2,%3};"
                        : "+f"(acc[ms][ns][0]), "+f"(acc[ms][ns][1]),
                          "+f"(acc[ms][ns][2]), "+f"(acc[ms][ns][3])
                        : "r"(a[ms][0]), "r"(a[ms][1]), "r"(a[ms][2]), "r"(a[ms][3]),
                          "r"(b[ns][0]), "r"(b[ns][1]));
                }
        }
        __syncthreads();
        st ^= 1;
    }

    // epilogue: store relu(v) fp16 + accumulate BN stats for rows < NN
    float s[4][2], q[4][2];
#pragma unroll
    for (int ns = 0; ns < 4; ++ns) { s[ns][0] = s[ns][1] = q[ns][0] = q[ns][1] = 0.f; }
#pragma unroll
    for (int ms = 0; ms < 4; ++ms) {
        int r0 = bm + warp_m * 64 + ms * 16 + (lane >> 2);
        bool ok0 = r0 < NN, ok1 = (r0 + 8) < NN;
#pragma unroll
        for (int ns = 0; ns < 4; ++ns) {
            int cc = bn + warp_n * 32 + ns * 8 + 2 * (lane & 3);
            float a0 = fmaxf(acc[ms][ns][0] + bias[cc + 0], 0.f);
            float a1 = fmaxf(acc[ms][ns][1] + bias[cc + 1], 0.f);
            float a2 = fmaxf(acc[ms][ns][2] + bias[cc + 0], 0.f);
            float a3 = fmaxf(acc[ms][ns][3] + bias[cc + 1], 0.f);
            __half2 h0 = __floats2half2_rn(a0, a1);
            __half2 h1 = __floats2half2_rn(a2, a3);
            *(__half2*)&C[(size_t)r0 * F1 + cc] = h0;
            *(__half2*)&C[(size_t)(r0 + 8) * F1 + cc] = h1;
            float m0 = ok0 ? a0 : 0.f;
            float m1 = ok0 ? a1 : 0.f;
            float m2 = ok1 ? a2 : 0.f;
            float m3 = ok1 ? a3 : 0.f;
            s[ns][0] += m0 + m2;
            s[ns][1] += m1 + m3;
            q[ns][0] += m0 * m0 + m2 * m2;
            q[ns][1] += m1 * m1 + m3 * m3;
        }
    }
#pragma unroll
    for (int ns = 0; ns < 4; ++ns)
#pragma unroll
        for (int par = 0; par < 2; ++par) {
            float sv = s[ns][par], qv = q[ns][par];
            sv += __shfl_xor_sync(0xffffffffu, sv, 4);
            sv += __shfl_xor_sync(0xffffffffu, sv, 8);
            sv += __shfl_xor_sync(0xffffffffu, sv, 16);
            qv += __shfl_xor_sync(0xffffffffu, qv, 4);
            qv += __shfl_xor_sync(0xffffffffu, qv, 8);
            qv += __shfl_xor_sync(0xffffffffu, qv, 16);
            if (lane < 4) {
                int colL = warp_n * 32 + ns * 8 + 2 * lane + par;
                atomicAdd(&sS[colL], sv);
                atomicAdd(&sQ[colL], qv);
            }
        }
    __syncthreads();
    if (tid < 128) {
        atomicAdd(&g_stats[bn + tid], sS[tid]);
        atomicAdd(&g_stats[F1 + bn + tid], sQ[tid]);
    }
}

// prep2: W2h = sc ⊙ W2c (Horner precombine fused), bias2 = sh @ W2c_k (+ b2)
__global__ void prep2_kernel(const float* __restrict__ W2, const float* __restrict__ b2,
                             const float* __restrict__ gamma, const float* __restrict__ beta) {
    int i = blockIdx.x * blockDim.x + threadIdx.x;
    const int SZ = F1 * F2;
    if (i >= SZ) return;
    int ch = i >> 7;      // 0..255
    int j = i & 127;
    float w0 = W2[i], w1 = W2[SZ + i], w2 = W2[2 * SZ + i], w3 = W2[3 * SZ + i];
    float c0 = w0 - w2;
    float c1 = w1 - 3.f * w3;
    float c2 = 2.f * w2;
    float c3 = 4.f * w3;
    float m = g_stats[ch] * (1.f / NN);
    float v = g_stats[F1 + ch] * (1.f / NN) - m * m;
    float inv = rsqrtf(v + 1e-5f);
    float sc = gamma[ch] * inv;
    float sh = beta[ch] - m * sc;
    g_W2h[i]          = __float2half(c0 * sc);
    g_W2h[SZ + i]     = __float2half(c1 * sc);
    g_W2h[2 * SZ + i] = __float2half(c2 * sc);
    g_W2h[3 * SZ + i] = __float2half(c3 * sc);
    atomicAdd(&g_bias2[j],           sh * c0 + ((ch == 0) ? b2[j] : 0.f));
    atomicAdd(&g_bias2[F2 + j],      sh * c1);
    atomicAdd(&g_bias2[2 * F2 + j],  sh * c2);
    atomicAdd(&g_bias2[3 * F2 + j],  sh * c3);
}

// GEMM2: C_k(h) = relu(out1) @ W2h_k + bias2_k ; k = blockIdx.y
__global__ __launch_bounds__(256)
void gemm2_f16(const __half* __restrict__ A) {
    __shared__ __align__(16) __half As[2 * ASTG];
    __shared__ __align__(16) __half Bs[2 * BSTG];

    const int tid = threadIdx.x;
    const int lane = tid & 31;
    const int wid = tid >> 5;
    const int warp_m = wid >> 2;
    const int warp_n = wid & 3;
    const int bm = blockIdx.x * 128;
    const int kblk = blockIdx.y;
    const __half* Wb0 = g_W2h + (size_t)kblk * F1 * F2;
    __half* C = g_Ck + (size_t)kblk * NPAD * F2;
    const int NIT = 8;   // 256/32

    float acc[4][4][4];
#pragma unroll
    for (int i = 0; i < 4; i++)
#pragma unroll
        for (int j = 0; j < 4; j++)
#pragma unroll
            for (int q = 0; q < 4; q++) acc[i][j][q] = 0.f;

    const unsigned asBase0 = (unsigned)__cvta_generic_to_shared(As);
    const unsigned bsBase0 = (unsigned)__cvta_generic_to_shared(Bs);
    const unsigned asFrag = asBase0 +
        ((warp_m * 64 + (lane & 15)) * PA + (lane >> 4) * 8) * 2;
    const int b_k = ((lane >> 3) & 1) * 8 + (lane & 7);
    const int b_n = (lane >> 4) * 8;

    auto load_tiles = [&](int st, int it) {
        int k0 = it * 32;
        const __half* Ab = A + (size_t)bm * F1 + k0;
        const __half* Wb = Wb0 + (size_t)k0 * F2;
        unsigned sA = asBase0 + st * ASTG * 2;
        unsigned sB = bsBase0 + st * BSTG * 2;
#pragma unroll
        for (int p = 0; p < 2; ++p) {
            int idx = p * 256 + tid;
            int row = idx >> 2, ch = (idx & 3) * 8;
            cp16(sA + (row * PA + ch) * 2, Ab + (size_t)row * F1 + ch);
            int kr = idx >> 4, bc = (idx & 15) * 8;
            cp16(sB + (kr * PB + bc) * 2, Wb + (size_t)kr * F2 + bc);
        }
        asm volatile("cp.async.commit_group;");
    };

    load_tiles(0, 0);
    int st = 0;
#pragma unroll 1
    for (int it = 0; it < NIT; ++it) {
        if (it + 1 < NIT) {
            load_tiles(st ^ 1, it + 1);
            asm volatile("cp.async.wait_group 1;");
        } else {
            asm volatile("cp.async.wait_group 0;");
        }
        __syncthreads();
#pragma unroll
        for (int ks = 0; ks < 2; ++ks) {
            unsigned a[4][4];
#pragma unroll
            for (int ms = 0; ms < 4; ++ms) {
                unsigned addr = asFrag + st * ASTG * 2 + ms * (16 * PA * 2) + ks * 32;
                asm volatile(
                    "ldmatrix.sync.aligned.m8n8.x4.shared.b16 {%0,%1,%2,%3}, [%4];"
                    : "=r"(a[ms][0]), "=r"(a[ms][1]), "=r"(a[ms][2]), "=r"(a[ms][3])
                    : "r"(addr));
            }
            unsigned b[4][2];
#pragma unroll
            for (int nsp = 0; nsp < 2; ++nsp) {
                int ncol = warp_n * 32 + nsp * 16 + b_n;
                unsigned baddr = bsBase0 + st * BSTG * 2 +
                                 ((ks * 16 + b_k) * PB + ncol) * 2;
                asm volatile(
                    "ldmatrix.sync.aligned.m8n8.x4.trans.shared.b16 {%0,%1,%2,%3}, [%4];"
                    : "=r"(b[2 * nsp][0]), "=r"(b[2 * nsp][1]),
                      "=r"(b[2 * nsp + 1][0]), "=r"(b[2 * nsp + 1][1])
                    : "r"(baddr));
            }
#pragma unroll
            for (int ms = 0; ms < 4; ++ms)
#pragma unroll
                for (int ns = 0; ns < 4; ++ns) {
                    asm volatile(
                        "mma.sync.aligned.m16n8k16.row.col.f32.f16.f16.f32 "
                        "{%0,%1,%2,%3}, {%4,%5,%6,%7}, {%8,%9}, {%0,%1,%2,%3};"
                        : "+f"(acc[ms][ns][0]), "+f"(acc[ms][ns][1]),
                          "+f"(acc[ms][ns][2]), "+f"(acc[ms][ns][3])
                        : "r"(a[ms][0]), "r"(a[ms][1]), "r"(a[ms][2]), "r"(a[ms][3]),
                          "r"(b[ns][0]), "r"(b[ns][1]));
                }
        }
        __syncthreads();
        st ^= 1;
    }

#pragma unroll
    for (int ms = 0; ms < 4; ++ms) {
        int r0 = bm + warp_m * 64 + ms * 16 + (lane >> 2);
#pragma unroll
        for (int ns = 0; ns < 4; ++ns) {
            int cc = warp_n * 32 + ns * 8 + 2 * (lane & 3);
            float bx = g_bias2[kblk * F2 + cc + 0];
            float by = g_bias2[kblk * F2 + cc + 1];
            __half2 h0 = __floats2half2_rn(acc[ms][ns][0] + bx, acc[ms][ns][1] + by);
            __half2 h1 = __floats2half2_rn(acc[ms][ns][2] + bx, acc[ms][ns][3] + by);
            *(__half2*)&C[(size_t)r0 * F2 + cc] = h0;
            *(__half2*)&C[(size_t)(r0 + 8) * F2 + cc] = h1;
        }
    }
}

// ---------------- BN2 stats ---------------------------------------------------
__global__ void stats_h128(const __half* __restrict__ X) {
    int col = threadIdx.x & 127;
    int ro = threadIdx.x >> 7;
    int r0 = blockIdx.x * 128 + ro;
    int rend = blockIdx.x * 128 + 128;
    if (rend > NN) rend = NN;
    float s = 0.f, s2 = 0.f;
    for (int r = r0; r < rend; r += 2) {
        float v = __half2float(X[(size_t)r * F2 + col]);
        v = v > 0.f ? v : 0.f;
        s += v;
        s2 = fmaf(v, v, s2);
    }
    atomicAdd(&g_stats2[col], s);
    atomicAdd(&g_stats2[F2 + col], s2);
}

// prep3: fold BN2 into final linear: Wlh = sc2 ⊙ Wlin, biasl = blin + sh2 @ Wlin^T
__global__ void prep3_kernel(const float* __restrict__ Wl, const float* __restrict__ bl,
                             const float* __restrict__ gamma, const float* __restrict__ beta) {
    int c = threadIdx.x;    // 128 threads
    float m = g_stats2[c] * (1.f / NN);
    float v = g_stats2[F2 + c] * (1.f / NN) - m * m;
    float inv = rsqrtf(v + 1e-5f);
    float sc = gamma[c] * inv;
    float sh = beta[c] - m * sc;
#pragma unroll
    for (int o = 0; o < 10; ++o) {
        float w = Wl[o * F2 + c];
        g_Wlh[o * F2 + c] = w * sc;
        float p = sh * w;
        p += __shfl_xor_sync(0xffffffffu, p, 16);
        p += __shfl_xor_sync(0xffffffffu, p, 8);
        p += __shfl_xor_sync(0xffffffffu, p, 4);
        p += __shfl_xor_sync(0xffffffffu, p, 2);
        p += __shfl_xor_sync(0xffffffffu, p, 1);
        if ((c & 31) == 0) atomicAdd(&g_biasl[o], p);
    }
    if (c < 10) atomicAdd(&g_biasl[c], bl[c]);
}

// final: out = relu(out2) @ Wlh^T + biasl, warp per node
__global__ void final_kernel(const __half* __restrict__ h, float* __restrict__ out) {
    int node = (blockIdx.x * blockDim.x + threadIdx.x) >> 5;
    if (node >= NN) return;
    int lane = threadIdx.x & 31;
    uint2 u = ((const uint2*)(h + (size_t)node * F2))[lane];
    float2 f0 = __half22float2(*(__half2*)&u.x);
    float2 f1 = __half22float2(*(__half2*)&u.y);
    float h0 = fmaxf(f0.x, 0.f);
    float h1 = fmaxf(f0.y, 0.f);
    float h2 = fmaxf(f1.x, 0.f);
    float h3 = fmaxf(f1.y, 0.f);
#pragma unroll
    for (int o = 0; o < 10; ++o) {
        float4 w = ((const float4*)(g_Wlh + o * F2))[lane];
        float p = h0 * w.x + h1 * w.y + h2 * w.z + h3 * w.w;
        p += __shfl_xor_sync(0xffffffffu, p, 16);
        p += __shfl_xor_sync(0xffffffffu, p, 8);
        p += __shfl_xor_sync(0xffffffffu, p, 4);
        p += __shfl_xor_sync(0xffffffffu, p, 2);
        p += __shfl_xor_sync(0xffffffffu, p, 1);
        if (lane == 0) out[node * 10 + o] = p + g_biasl[o];
    }
}

// ---------------- launch ------------------------------------------------------
extern "C" void kernel_launch(void* const* d_in, const int* in_sizes, int n_in,
                              void* d_out, int out_size) {
    const float* x      = (const float*)d_in[0];
    const int*   ei     = (const int*)d_in[1];
    const float* ew     = (const float*)d_in[2];
    const float* W1     = (const float*)d_in[3];
    const float* b1     = (const float*)d_in[4];
    const float* W2     = (const float*)d_in[5];
    const float* b2     = (const float*)d_in[6];
    const float* gamma1 = (const float*)d_in[7];
    const float* beta1  = (const float*)d_in[8];
    const float* gamma2 = (const float*)d_in[9];
    const float* beta2  = (const float*)d_in[10];
    const float* Wlin   = (const float*)d_in[11];
    const float* blin   = (const float*)d_in[12];
    float* out = (float*)d_out;

    const int* row = ei;
    const int* col = ei + EE;

    float *deg;
    int *cnt;
    __half *TxA, *out1, *Ck, *out2;
    cudaGetSymbolAddress((void**)&deg,  g_deg);
    cudaGetSymbolAddress((void**)&cnt,  g_cnt);
    cudaGetSymbolAddress((void**)&TxA,  g_TxA);
    cudaGetSymbolAddress((void**)&out1, g_out1);
    cudaGetSymbolAddress((void**)&Ck,   g_Ck);
    cudaGetSymbolAddress((void**)&out2, g_out2);

    const int EB = (EE + 255) / 256;
    const int SB = (NN * 32 + 255) / 256;

    // ---- CSR build ----
    cudaMemsetAsync(deg, 0, NPAD * sizeof(float));
    cudaMemsetAsync(cnt, 0, NPAD * sizeof(int));

    deg_cnt_kernel<<<EB, 256>>>(row, col, ew);
    scan_dis_kernel<<<1, 1024>>>();
    scatter_kernel<<<EB, 256>>>(row, col, ew);

    cvt_x_kernel<<<(NN * 32 + 255) / 256, 256>>>(x, TxA);
    w1cvt_kernel<<<(4 * F0 * F1 / 4 + 255) / 256, 256>>>(W1);

    // ---- layer 1: Chebyshev recursion at F=128 (fp16 features) ----
    __half* A0 = TxA;
    __half* A1 = TxA + (size_t)NPAD * F0;
    __half* A2 = TxA + (size_t)2 * NPAD * F0;
    __half* A3 = TxA + (size_t)3 * NPAD * F0;
    spmm_h<<<SB, 256>>>(A0, A1, nullptr, nullptr, 1.f);
    spmm_h<<<SB, 256>>>(A1, A2, A0, nullptr, 2.f);
    spmm_h<<<SB, 256>>>(A2, A3, A1, nullptr, 2.f);

    gemm1_f16<<<dim3(NPAD / 128, 2), 256>>>(TxA, b1, out1);

    // ---- layer 2: Horner form with BN folded into weights ----
    prep2_kernel<<<(F1 * F2 + 255) / 256, 256>>>(W2, b2, gamma1, beta1);
    gemm2_f16<<<dim3(NPAD / 128, 4), 256>>>(out1);

    __half* C0 = Ck;
    __half* C1 = Ck + (size_t)NPAD * F2;
    __half* C2 = Ck + (size_t)2 * NPAD * F2;
    __half* C3 = Ck + (size_t)3 * NPAD * F2;
    __half* t1 = TxA;
    __half* t2 = TxA + (size_t)NPAD * F0;
    spmm_h<<<SB, 256>>>(C3, t1, nullptr, C2, 1.f);
    spmm_h<<<SB, 256>>>(t1, t2, nullptr, C1, 1.f);
    spmm_h<<<SB, 256>>>(t2, out2, nullptr, C0, 1.f);

    stats_h128<<<157, 256>>>(out2);
    prep3_kernel<<<1, 128>>>(Wlin, blin, gamma2, beta2);

    final_kernel<<<SB, 256>>>(out2, out);
}

// round 11
// speedup vs baseline: 1.4069x; 1.0140x over previous
#include <cuda_runtime.h>
#include <cuda_fp16.h>
#include <cstdint>

// Problem constants
#define NN   20000
#define EE   640000
#define F0   128
#define F1   256
#define F2   128
#define NPAD 20096   // 157 * 128
#define MAXD 128     // ELL slots per node (Poisson(32) overflow prob ~1e-40)

// ---------------- scratch (device globals, zero at module load) -------------
__device__ __align__(16) unsigned g_degcnt[2 * NPAD];   // [0,NPAD)=deg(float), [NPAD,..)=cnt(int)
__device__ __align__(16) int2   g_pack[NPAD * MAXD];    // ELL: (src_row, w) per dst
__device__ __align__(16) __half g_TxA[4 * NPAD * F0];   // fp16 feature stacks
__device__ __align__(16) __half g_out1[NPAD * F1];      // relu(GEMM1 out), fp16
__device__ __align__(16) __half g_Ck[4 * NPAD * F2];    // layer2 Horner coeffs
__device__ __align__(16) __half g_out2[NPAD * F2];
__device__ __align__(16) __half g_W1h[4 * F0 * F1];     // W1 in fp16
__device__ __align__(16) __half g_W2h[4 * F1 * F2];     // sc ⊙ W2c (fp16)
__device__ __align__(16) float  g_bias2[4 * F2];        // sh @ W2c_k (+ b2)
__device__ __align__(16) float  g_Wlh[10 * F2];         // sc2 ⊙ Wlin
__device__ __align__(16) float  g_biasl[16];            // blin + sh2 @ Wlin^T
__device__ __align__(16) float  g_stats[2 * F1];        // layer1 sum/sumsq
__device__ __align__(16) float  g_stats2[2 * F2];       // layer2 sum/sumsq

// ---------------- ELL build: single edge pass --------------------------------
__global__ void pass1_kernel(const int* __restrict__ row,
                             const int* __restrict__ col,
                             const float* __restrict__ ew) {
    int e = blockIdx.x * blockDim.x + threadIdx.x;
    if (e >= EE) return;
    int r = row[e], c = col[e];
    float w = (r == c) ? 0.f : ew[e];
    float* deg = (float*)g_degcnt;
    int*   cnt = (int*)(g_degcnt + NPAD);
    if (w != 0.f) atomicAdd(&deg[r], w);
    int slot = atomicAdd(&cnt[c], 1);
    int2 p;
    p.x = r;
    p.y = __float_as_int(w);
    g_pack[c * MAXD + slot] = p;
}

// transform: wn = -rsqrt(deg[r]) * w * rsqrt(deg[c]) in-place; zero stat buffers
__global__ void transform_kernel() {
    int tid = threadIdx.x;
    if (blockIdx.x == 0) {
        for (int i = tid; i < 2 * F1; i += 256) g_stats[i] = 0.f;
        for (int i = tid; i < 2 * F2; i += 256) g_stats2[i] = 0.f;
        for (int i = tid; i < 4 * F2; i += 256) g_bias2[i] = 0.f;
        if (tid < 16) g_biasl[tid] = 0.f;
    }
    int node = (blockIdx.x * blockDim.x + tid) >> 5;
    if (node >= NN) return;
    int lane = tid & 31;
    const float* deg = (const float*)g_degcnt;
    const int*   cnt = (const int*)(g_degcnt + NPAD);
    float dc = deg[node];
    float disc = (dc > 0.f) ? rsqrtf(dc) : 0.f;
    int n = cnt[node];
    int base = node * MAXD;
    for (int i = lane; i < n; i += 32) {
        int2 p = g_pack[base + i];
        float w = __int_as_float(p.y);
        float dr = deg[p.x];
        float disr = (dr > 0.f) ? rsqrtf(dr) : 0.f;
        p.y = __float_as_int(-disr * w * disc);
        g_pack[base + i] = p;
    }
}

// merged converts: x (fp32->fp16 into TxA block 0) and W1 (fp32->fp16)
#define XCNT (NN * 32)            // uint2 elements for x
#define WCNT (4 * F0 * F1 / 4)    // uint2 elements for W1
__global__ void cvt_kernel(const float* __restrict__ x, const float* __restrict__ W1) {
    int i = blockIdx.x * blockDim.x + threadIdx.x;
    if (i >= XCNT + WCNT) return;
    const float4* src;
    uint2* dst;
    if (i < XCNT) {
        src = (const float4*)x + i;
        dst = (uint2*)g_TxA + i;
    } else {
        src = (const float4*)W1 + (i - XCNT);
        dst = (uint2*)g_W1h + (i - XCNT);
    }
    float4 v = *src;
    uint2 o;
    __half2 h0 = __floats2half2_rn(v.x, v.y);
    __half2 h1 = __floats2half2_rn(v.z, v.w);
    o.x = *(unsigned*)&h0;
    o.y = *(unsigned*)&h1;
    *dst = o;
}

// ---- gather SPMM (fp16, F=128): out = alpha*(L@in) - sub + add --------------
__device__ __forceinline__ void hfma4(float4& acc, float w, uint2 u) {
    float2 f0 = __half22float2(*(__half2*)&u.x);
    float2 f1 = __half22float2(*(__half2*)&u.y);
    acc.x = fmaf(w, f0.x, acc.x);
    acc.y = fmaf(w, f0.y, acc.y);
    acc.z = fmaf(w, f1.x, acc.z);
    acc.w = fmaf(w, f1.y, acc.w);
}

__global__ void spmm_h(const __half* __restrict__ in, __half* __restrict__ out,
                       const __half* __restrict__ sub,
                       const __half* __restrict__ add, float alpha) {
    int node = (blockIdx.x * blockDim.x + threadIdx.x) >> 5;
    if (node >= NN) return;
    int lane = threadIdx.x & 31;
    int beg = node * MAXD;
    int end = beg + ((const int*)(g_degcnt + NPAD))[node];

    const uint2* base = (const uint2*)in + lane;
    float4 acc0 = make_float4(0.f, 0.f, 0.f, 0.f);
    float4 acc1 = make_float4(0.f, 0.f, 0.f, 0.f);
    float4 acc2 = make_float4(0.f, 0.f, 0.f, 0.f);
    float4 acc3 = make_float4(0.f, 0.f, 0.f, 0.f);

    int i = beg;
    for (; i + 4 <= end; i += 4) {
        int2 p0 = g_pack[i + 0], p1 = g_pack[i + 1];
        int2 p2 = g_pack[i + 2], p3 = g_pack[i + 3];
        uint2 u0 = base[(size_t)p0.x * 32];
        uint2 u1 = base[(size_t)p1.x * 32];
        uint2 u2 = base[(size_t)p2.x * 32];
        uint2 u3 = base[(size_t)p3.x * 32];
        hfma4(acc0, __int_as_float(p0.y), u0);
        hfma4(acc1, __int_as_float(p1.y), u1);
        hfma4(acc2, __int_as_float(p2.y), u2);
        hfma4(acc3, __int_as_float(p3.y), u3);
    }
    for (; i < end; ++i) {
        int2 p0 = g_pack[i];
        uint2 u0 = base[(size_t)p0.x * 32];
        hfma4(acc0, __int_as_float(p0.y), u0);
    }
    float4 r;
    r.x = alpha * ((acc0.x + acc1.x) + (acc2.x + acc3.x));
    r.y = alpha * ((acc0.y + acc1.y) + (acc2.y + acc3.y));
    r.z = alpha * ((acc0.z + acc1.z) + (acc2.z + acc3.z));
    r.w = alpha * ((acc0.w + acc1.w) + (acc2.w + acc3.w));
    size_t oidx = (size_t)node * 32 + lane;
    if (add) {
        uint2 u = ((const uint2*)add)[oidx];
        float2 f0 = __half22float2(*(__half2*)&u.x);
        float2 f1 = __half22float2(*(__half2*)&u.y);
        r.x += f0.x; r.y += f0.y; r.z += f1.x; r.w += f1.y;
    }
    if (sub) {
        uint2 u = ((const uint2*)sub)[oidx];
        float2 f0 = __half22float2(*(__half2*)&u.x);
        float2 f1 = __half22float2(*(__half2*)&u.y);
        r.x -= f0.x; r.y -= f0.y; r.z -= f1.x; r.w -= f1.y;
    }
    uint2 o;
    __half2 h0 = __floats2half2_rn(r.x, r.y);
    __half2 h1 = __floats2half2_rn(r.z, r.w);
    o.x = *(unsigned*)&h0;
    o.y = *(unsigned*)&h1;
    ((uint2*)out)[oidx] = o;
}

// ---------------- fp16 tensor-core GEMMs, cp.async double-buffered -----------
#define PA 40      // A smem pitch in halves
#define PB 136     // B smem pitch in halves
#define ASTG (128 * PA)
#define BSTG (32 * PB)

__device__ __forceinline__ void cp16(unsigned sdst, const void* gsrc) {
    asm volatile("cp.async.cg.shared.global [%0], [%1], 16;" :: "r"(sdst), "l"(gsrc));
}

// GEMM1: out1(h) = relu( sum_chunk TxA_chunk @ W1h_chunk + b1 ) ; fused BN1 stats
__global__ __launch_bounds__(256)
void gemm1_f16(const __half* __restrict__ A, const float* __restrict__ bias,
               __half* __restrict__ C) {
    __shared__ __align__(16) __half As[2 * ASTG];
    __shared__ __align__(16) __half Bs[2 * BSTG];
    __shared__ float sS[128], sQ[128];

    const int tid = threadIdx.x;
    const int lane = tid & 31;
    const int wid = tid >> 5;
    const int warp_m = wid >> 2;
    const int warp_n = wid & 3;
    const int bm = blockIdx.x * 128;
    const int bn = blockIdx.y * 128;
    const int NIT = 16;

    if (tid < 128) { sS[tid] = 0.f; sQ[tid] = 0.f; }

    float acc[4][4][4];
#pragma unroll
    for (int i = 0; i < 4; i++)
#pragma unroll
        for (int j = 0; j < 4; j++)
#pragma unroll
            for (int q = 0; q < 4; q++) acc[i][j][q] = 0.f;

    const unsigned asBase0 = (unsigned)__cvta_generic_to_shared(As);
    const unsigned bsBase0 = (unsigned)__cvta_generic_to_shared(Bs);
    const unsigned asFrag = asBase0 +
        ((warp_m * 64 + (lane & 15)) * PA + (lane >> 4) * 8) * 2;
    const int b_k = ((lane >> 3) & 1) * 8 + (lane & 7);
    const int b_n = (lane >> 4) * 8;

    auto load_tiles = [&](int st, int it) {
        int chunk = it >> 2;
        int k0 = (it & 3) * 32;
        const __half* Ab = A + (size_t)chunk * NPAD * F0 + (size_t)bm * F0 + k0;
        const __half* Wb = g_W1h + (size_t)chunk * F0 * F1 + (size_t)k0 * F1 + bn;
        unsigned sA = asBase0 + st * ASTG * 2;
        unsigned sB = bsBase0 + st * BSTG * 2;
#pragma unroll
        for (int p = 0; p < 2; ++p) {
            int idx = p * 256 + tid;
            int rrow = idx >> 2, ch = (idx & 3) * 8;
            cp16(sA + (rrow * PA + ch) * 2, Ab + (size_t)rrow * F0 + ch);
            int kr = idx >> 4, bc = (idx & 15) * 8;
            cp16(sB + (kr * PB + bc) * 2, Wb + (size_t)kr * F1 + bc);
        }
        asm volatile("cp.async.commit_group;");
    };

    load_tiles(0, 0);
    int st = 0;
#pragma unroll 1
    for (int it = 0; it < NIT; ++it) {
        if (it + 1 < NIT) {
            load_tiles(st ^ 1, it + 1);
            asm volatile("cp.async.wait_group 1;");
        } else {
            asm volatile("cp.async.wait_group 0;");
        }
        __syncthreads();
#pragma unroll
        for (int ks = 0; ks < 2; ++ks) {
            unsigned a[4][4];
#pragma unroll
            for (int ms = 0; ms < 4; ++ms) {
                unsigned addr = asFrag + st * ASTG * 2 + ms * (16 * PA * 2) + ks * 32;
                asm volatile(
                    "ldmatrix.sync.aligned.m8n8.x4.shared.b16 {%0,%1,%2,%3}, [%4];"
                    : "=r"(a[ms][0]), "=r"(a[ms][1]), "=r"(a[ms][2]), "=r"(a[ms][3])
                    : "r"(addr));
            }
            unsigned b[4][2];
#pragma unroll
            for (int nsp = 0; nsp < 2; ++nsp) {
                int ncol = warp_n * 32 + nsp * 16 + b_n;
                unsigned baddr = bsBase0 + st * BSTG * 2 +
                                 ((ks * 16 + b_k) * PB + ncol) * 2;
                asm volatile(
                    "ldmatrix.sync.aligned.m8n8.x4.trans.shared.b16 {%0,%1,%2,%3}, [%4];"
                    : "=r"(b[2 * nsp][0]), "=r"(b[2 * nsp][1]),
                      "=r"(b[2 * nsp + 1][0]), "=r"(b[2 * nsp + 1][1])
                    : "r"(baddr));
            }
#pragma unroll
            for (int ms = 0; ms < 4; ++ms)
#pragma unroll
                for (int ns = 0; ns < 4; ++ns) {
                    asm volatile(
                        "mma.sync.aligned.m16n8k16.row.col.f32.f16.f16.f32 "
                        "{%0,%1,%2,%3}, {%4,%5,%6,%7}, {%8,%9}, {%0,%1,%2,%3};"
                        : "+f"(acc[ms][ns][0]), "+f"(acc[ms][ns][1]),
                          "+f"(acc[ms][ns][2]), "+f"(acc[ms][ns][3])
                        : "r"(a[ms][0]), "r"(a[ms][1]), "r"(a[ms][2]), "r"(a[ms][3]),
                          "r"(b[ns][0]), "r"(b[ns][1]));
                }
        }
        __syncthreads();
        st ^= 1;
    }

    // epilogue: store relu(v) fp16 + accumulate BN stats for rows < NN
    float s[4][2], q[4][2];
#pragma unroll
    for (int ns = 0; ns < 4; ++ns) { s[ns][0] = s[ns][1] = q[ns][0] = q[ns][1] = 0.f; }
#pragma unroll
    for (int ms = 0; ms < 4; ++ms) {
        int r0 = bm + warp_m * 64 + ms * 16 + (lane >> 2);
        bool ok0 = r0 < NN, ok1 = (r0 + 8) < NN;
#pragma unroll
        for (int ns = 0; ns < 4; ++ns) {
            int cc = bn + warp_n * 32 + ns * 8 + 2 * (lane & 3);
            float a0 = fmaxf(acc[ms][ns][0] + bias[cc + 0], 0.f);
            float a1 = fmaxf(acc[ms][ns][1] + bias[cc + 1], 0.f);
            float a2 = fmaxf(acc[ms][ns][2] + bias[cc + 0], 0.f);
            float a3 = fmaxf(acc[ms][ns][3] + bias[cc + 1], 0.f);
            __half2 h0 = __floats2half2_rn(a0, a1);
            __half2 h1 = __floats2half2_rn(a2, a3);
            *(__half2*)&C[(size_t)r0 * F1 + cc] = h0;
            *(__half2*)&C[(size_t)(r0 + 8) * F1 + cc] = h1;
            float m0 = ok0 ? a0 : 0.f;
            float m1 = ok0 ? a1 : 0.f;
            float m2 = ok1 ? a2 : 0.f;
            float m3 = ok1 ? a3 : 0.f;
            s[ns][0] += m0 + m2;
            s[ns][1] += m1 + m3;
            q[ns][0] += m0 * m0 + m2 * m2;
            q[ns][1] += m1 * m1 + m3 * m3;
        }
    }
#pragma unroll
    for (int ns = 0; ns < 4; ++ns)
#pragma unroll
        for (int par = 0; par < 2; ++par) {
            float sv = s[ns][par], qv = q[ns][par];
            sv += __shfl_xor_sync(0xffffffffu, sv, 4);
            sv += __shfl_xor_sync(0xffffffffu, sv, 8);
            sv += __shfl_xor_sync(0xffffffffu, sv, 16);
            qv += __shfl_xor_sync(0xffffffffu, qv, 4);
            qv += __shfl_xor_sync(0xffffffffu, qv, 8);
            qv += __shfl_xor_sync(0xffffffffu, qv, 16);
            if (lane < 4) {
                int colL = warp_n * 32 + ns * 8 + 2 * lane + par;
                atomicAdd(&sS[colL], sv);
                atomicAdd(&sQ[colL], qv);
            }
        }
    __syncthreads();
    if (tid < 128) {
        atomicAdd(&g_stats[bn + tid], sS[tid]);
        atomicAdd(&g_stats[F1 + bn + tid], sQ[tid]);
    }
}

// prep2: W2h = sc ⊙ W2c (Horner precombine fused), bias2 = sh @ W2c_k (+ b2)
__global__ void prep2_kernel(const float* __restrict__ W2, const float* __restrict__ b2,
                             const float* __restrict__ gamma, const float* __restrict__ beta) {
    int i = blockIdx.x * blockDim.x + threadIdx.x;
    const int SZ = F1 * F2;
    if (i >= SZ) return;
    int ch = i >> 7;
    int j = i & 127;
    float w0 = W2[i], w1 = W2[SZ + i], w2 = W2[2 * SZ + i], w3 = W2[3 * SZ + i];
    float c0 = w0 - w2;
    float c1 = w1 - 3.f * w3;
    float c2 = 2.f * w2;
    float c3 = 4.f * w3;
    float m = g_stats[ch] * (1.f / NN);
    float v = g_stats[F1 + ch] * (1.f / NN) - m * m;
    float inv = rsqrtf(v + 1e-5f);
    float sc = gamma[ch] * inv;
    float sh = beta[ch] - m * sc;
    g_W2h[i]          = __float2half(c0 * sc);
    g_W2h[SZ + i]     = __float2half(c1 * sc);
    g_W2h[2 * SZ + i] = __float2half(c2 * sc);
    g_W2h[3 * SZ + i] = __float2half(c3 * sc);
    atomicAdd(&g_bias2[j],           sh * c0 + ((ch == 0) ? b2[j] : 0.f));
    atomicAdd(&g_bias2[F2 + j],      sh * c1);
    atomicAdd(&g_bias2[2 * F2 + j],  sh * c2);
    atomicAdd(&g_bias2[3 * F2 + j],  sh * c3);
}

// GEMM2: C_k(h) = relu(out1) @ W2h_k + bias2_k ; k = blockIdx.y
__global__ __launch_bounds__(256)
void gemm2_f16(const __half* __restrict__ A) {
    __shared__ __align__(16) __half As[2 * ASTG];
    __shared__ __align__(16) __half Bs[2 * BSTG];

    const int tid = threadIdx.x;
    const int lane = tid & 31;
    const int wid = tid >> 5;
    const int warp_m = wid >> 2;
    const int warp_n = wid & 3;
    const int bm = blockIdx.x * 128;
    const int kblk = blockIdx.y;
    const __half* Wb0 = g_W2h + (size_t)kblk * F1 * F2;
    __half* C = g_Ck + (size_t)kblk * NPAD * F2;
    const int NIT = 8;

    float acc[4][4][4];
#pragma unroll
    for (int i = 0; i < 4; i++)
#pragma unroll
        for (int j = 0; j < 4; j++)
#pragma unroll
            for (int q = 0; q < 4; q++) acc[i][j][q] = 0.f;

    const unsigned asBase0 = (unsigned)__cvta_generic_to_shared(As);
    const unsigned bsBase0 = (unsigned)__cvta_generic_to_shared(Bs);
    const unsigned asFrag = asBase0 +
        ((warp_m * 64 + (lane & 15)) * PA + (lane >> 4) * 8) * 2;
    const int b_k = ((lane >> 3) & 1) * 8 + (lane & 7);
    const int b_n = (lane >> 4) * 8;

    auto load_tiles = [&](int st, int it) {
        int k0 = it * 32;
        const __half* Ab = A + (size_t)bm * F1 + k0;
        const __half* Wb = Wb0 + (size_t)k0 * F2;
        unsigned sA = asBase0 + st * ASTG * 2;
        unsigned sB = bsBase0 + st * BSTG * 2;
#pragma unroll
        for (int p = 0; p < 2; ++p) {
            int idx = p * 256 + tid;
            int rrow = idx >> 2, ch = (idx & 3) * 8;
            cp16(sA + (rrow * PA + ch) * 2, Ab + (size_t)rrow * F1 + ch);
            int kr = idx >> 4, bc = (idx & 15) * 8;
            cp16(sB + (kr * PB + bc) * 2, Wb + (size_t)kr * F2 + bc);
        }
        asm volatile("cp.async.commit_group;");
    };

    load_tiles(0, 0);
    int st = 0;
#pragma unroll 1
    for (int it = 0; it < NIT; ++it) {
        if (it + 1 < NIT) {
            load_tiles(st ^ 1, it + 1);
            asm volatile("cp.async.wait_group 1;");
        } else {
            asm volatile("cp.async.wait_group 0;");
        }
        __syncthreads();
#pragma unroll
        for (int ks = 0; ks < 2; ++ks) {
            unsigned a[4][4];
#pragma unroll
            for (int ms = 0; ms < 4; ++ms) {
                unsigned addr = asFrag + st * ASTG * 2 + ms * (16 * PA * 2) + ks * 32;
                asm volatile(
                    "ldmatrix.sync.aligned.m8n8.x4.shared.b16 {%0,%1,%2,%3}, [%4];"
                    : "=r"(a[ms][0]), "=r"(a[ms][1]), "=r"(a[ms][2]), "=r"(a[ms][3])
                    : "r"(addr));
            }
            unsigned b[4][2];
#pragma unroll
            for (int nsp = 0; nsp < 2; ++nsp) {
                int ncol = warp_n * 32 + nsp * 16 + b_n;
                unsigned baddr = bsBase0 + st * BSTG * 2 +
                                 ((ks * 16 + b_k) * PB + ncol) * 2;
                asm volatile(
                    "ldmatrix.sync.aligned.m8n8.x4.trans.shared.b16 {%0,%1,%2,%3}, [%4];"
                    : "=r"(b[2 * nsp][0]), "=r"(b[2 * nsp][1]),
                      "=r"(b[2 * nsp + 1][0]), "=r"(b[2 * nsp + 1][1])
                    : "r"(baddr));
            }
#pragma unroll
            for (int ms = 0; ms < 4; ++ms)
#pragma unroll
                for (int ns = 0; ns < 4; ++ns) {
                    asm volatile(
                        "mma.sync.aligned.m16n8k16.row.col.f32.f16.f16.f32 "
                        "{%0,%1,%2,%3}, {%4,%5,%6,%7}, {%8,%9}, {%0,%1,%2,%3};"
                        : "+f"(acc[ms][ns][0]), "+f"(acc[ms][ns][1]),
                          "+f"(acc[ms][ns][2]), "+f"(acc[ms][ns][3])
                        : "r"(a[ms][0]), "r"(a[ms][1]), "r"(a[ms][2]), "r"(a[ms][3]),
                          "r"(b[ns][0]), "r"(b[ns][1]));
                }
        }
        __syncthreads();
        st ^= 1;
    }

#pragma unroll
    for (int ms = 0; ms < 4; ++ms) {
        int r0 = bm + warp_m * 64 + ms * 16 + (lane >> 2);
#pragma unroll
        for (int ns = 0; ns < 4; ++ns) {
            int cc = warp_n * 32 + ns * 8 + 2 * (lane & 3);
            float bx = g_bias2[kblk * F2 + cc + 0];
            float by = g_bias2[kblk * F2 + cc + 1];
            __half2 h0 = __floats2half2_rn(acc[ms][ns][0] + bx, acc[ms][ns][1] + by);
            __half2 h1 = __floats2half2_rn(acc[ms][ns][2] + bx, acc[ms][ns][3] + by);
            *(__half2*)&C[(size_t)r0 * F2 + cc] = h0;
            *(__half2*)&C[(size_t)(r0 + 8) * F2 + cc] = h1;
        }
    }
}

// ---------------- BN2 stats ---------------------------------------------------
__global__ void stats_h128(const __half* __restrict__ X) {
    int col = threadIdx.x & 127;
    int ro = threadIdx.x >> 7;
    int r0 = blockIdx.x * 128 + ro;
    int rend = blockIdx.x * 128 + 128;
    if (rend > NN) rend = NN;
    float s = 0.f, s2 = 0.f;
    for (int r = r0; r < rend; r += 2) {
        float v = __half2float(X[(size_t)r * F2 + col]);
        v = v > 0.f ? v : 0.f;
        s += v;
        s2 = fmaf(v, v, s2);
    }
    atomicAdd(&g_stats2[col], s);
    atomicAdd(&g_stats2[F2 + col], s2);
}

// prep3: fold BN2 into final linear
__global__ void prep3_kernel(const float* __restrict__ Wl, const float* __restrict__ bl,
                             const float* __restrict__ gamma, const float* __restrict__ beta) {
    int c = threadIdx.x;    // 128 threads
    float m = g_stats2[c] * (1.f / NN);
    float v = g_stats2[F2 + c] * (1.f / NN) - m * m;
    float inv = rsqrtf(v + 1e-5f);
    float sc = gamma[c] * inv;
    float sh = beta[c] - m * sc;
#pragma unroll
    for (int o = 0; o < 10; ++o) {
        float w = Wl[o * F2 + c];
        g_Wlh[o * F2 + c] = w * sc;
        float p = sh * w;
        p += __shfl_xor_sync(0xffffffffu, p, 16);
        p += __shfl_xor_sync(0xffffffffu, p, 8);
        p += __shfl_xor_sync(0xffffffffu, p, 4);
        p += __shfl_xor_sync(0xffffffffu, p, 2);
        p += __shfl_xor_sync(0xffffffffu, p, 1);
        if ((c & 31) == 0) atomicAdd(&g_biasl[o], p);
    }
    if (c < 10) atomicAdd(&g_biasl[c], bl[c]);
}

// final: out = relu(out2) @ Wlh^T + biasl, warp per node
__global__ void final_kernel(const __half* __restrict__ h, float* __restrict__ out) {
    int node = (blockIdx.x * blockDim.x + threadIdx.x) >> 5;
    if (node >= NN) return;
    int lane = threadIdx.x & 31;
    uint2 u = ((const uint2*)(h + (size_t)node * F2))[lane];
    float2 f0 = __half22float2(*(__half2*)&u.x);
    float2 f1 = __half22float2(*(__half2*)&u.y);
    float h0 = fmaxf(f0.x, 0.f);
    float h1 = fmaxf(f0.y, 0.f);
    float h2 = fmaxf(f1.x, 0.f);
    float h3 = fmaxf(f1.y, 0.f);
#pragma unroll
    for (int o = 0; o < 10; ++o) {
        float4 w = ((const float4*)(g_Wlh + o * F2))[lane];
        float p = h0 * w.x + h1 * w.y + h2 * w.z + h3 * w.w;
        p += __shfl_xor_sync(0xffffffffu, p, 16);
        p += __shfl_xor_sync(0xffffffffu, p, 8);
        p += __shfl_xor_sync(0xffffffffu, p, 4);
        p += __shfl_xor_sync(0xffffffffu, p, 2);
        p += __shfl_xor_sync(0xffffffffu, p, 1);
        if (lane == 0) out[node * 10 + o] = p + g_biasl[o];
    }
}

// ---------------- launch ------------------------------------------------------
extern "C" void kernel_launch(void* const* d_in, const int* in_sizes, int n_in,
                              void* d_out, int out_size) {
    const float* x      = (const float*)d_in[0];
    const int*   ei     = (const int*)d_in[1];
    const float* ew     = (const float*)d_in[2];
    const float* W1     = (const float*)d_in[3];
    const float* b1     = (const float*)d_in[4];
    const float* W2     = (const float*)d_in[5];
    const float* b2     = (const float*)d_in[6];
    const float* gamma1 = (const float*)d_in[7];
    const float* beta1  = (const float*)d_in[8];
    const float* gamma2 = (const float*)d_in[9];
    const float* beta2  = (const float*)d_in[10];
    const float* Wlin   = (const float*)d_in[11];
    const float* blin   = (const float*)d_in[12];
    float* out = (float*)d_out;

    const int* row = ei;
    const int* col = ei + EE;

    unsigned* degcnt;
    __half *TxA, *out1, *Ck, *out2;
    cudaGetSymbolAddress((void**)&degcnt, g_degcnt);
    cudaGetSymbolAddress((void**)&TxA,  g_TxA);
    cudaGetSymbolAddress((void**)&out1, g_out1);
    cudaGetSymbolAddress((void**)&Ck,   g_Ck);
    cudaGetSymbolAddress((void**)&out2, g_out2);

    const int EB = (EE + 255) / 256;
    const int SB = (NN * 32 + 255) / 256;

    // ---- ELL build ----
    cudaMemsetAsync(degcnt, 0, 2 * NPAD * sizeof(unsigned));
    pass1_kernel<<<EB, 256>>>(row, col, ew);
    transform_kernel<<<SB, 256>>>();
    cvt_kernel<<<(XCNT + WCNT + 255) / 256, 256>>>(x, W1);

    // ---- layer 1: Chebyshev recursion at F=128 (fp16 features) ----
    __half* A0 = TxA;
    __half* A1 = TxA + (size_t)NPAD * F0;
    __half* A2 = TxA + (size_t)2 * NPAD * F0;
    __half* A3 = TxA + (size_t)3 * NPAD * F0;
    spmm_h<<<SB, 256>>>(A0, A1, nullptr, nullptr, 1.f);
    spmm_h<<<SB, 256>>>(A1, A2, A0, nullptr, 2.f);
    spmm_h<<<SB, 256>>>(A2, A3, A1, nullptr, 2.f);

    gemm1_f16<<<dim3(NPAD / 128, 2), 256>>>(TxA, b1, out1);

    // ---- layer 2: Horner form with BN folded into weights ----
    prep2_kernel<<<(F1 * F2 + 255) / 256, 256>>>(W2, b2, gamma1, beta1);
    gemm2_f16<<<dim3(NPAD / 128, 4), 256>>>(out1);

    __half* C0 = Ck;
    __half* C1 = Ck + (size_t)NPAD * F2;
    __half* C2 = Ck + (size_t)2 * NPAD * F2;
    __half* C3 = Ck + (size_t)3 * NPAD * F2;
    __half* t1 = TxA;
    __half* t2 = TxA + (size_t)NPAD * F0;
    spmm_h<<<SB, 256>>>(C3, t1, nullptr, C2, 1.f);
    spmm_h<<<SB, 256>>>(t1, t2, nullptr, C1, 1.f);
    spmm_h<<<SB, 256>>>(t2, out2, nullptr, C0, 1.f);

    stats_h128<<<157, 256>>>(out2);
    prep3_kernel<<<1, 128>>>(Wlin, blin, gamma2, beta2);

    final_kernel<<<SB, 256>>>(out2, out);
}

// round 12
// speedup vs baseline: 1.6102x; 1.1445x over previous
#include <cuda_runtime.h>
#include <cuda_fp16.h>
#include <cstdint>

// Problem constants
#define NN   20000
#define EE   640000
#define F0   128
#define F1   256
#define F2   128
#define NPAD 20096   // 157 * 128
#define MAXD 128     // ELL slots per node

// ---------------- scratch (device globals, zero at module load) -------------
__device__ __align__(16) unsigned g_degcnt[2 * NPAD];   // deg(float) | cnt(int)
__device__ __align__(16) int2   g_pack[NPAD * MAXD];    // ELL: (src_row, w) per dst
__device__ __align__(16) __half g_TxA[4 * NPAD * F0];
__device__ __align__(16) __half g_out1[NPAD * F1];
__device__ __align__(16) __half g_Ck[4 * NPAD * F2];
__device__ __align__(16) __half g_out2[NPAD * F2];
__device__ __align__(16) __half g_W1h[4 * F0 * F1];
__device__ __align__(16) __half g_W2h[4 * F1 * F2];
__device__ __align__(16) float  g_bias2[4 * F2];
__device__ __align__(16) float  g_Wlh[10 * F2];
__device__ __align__(16) float  g_biasl[16];
__device__ __align__(16) float  g_stats[2 * F1];
__device__ __align__(16) float  g_stats2[2 * F2];

// ---------------- ELL build: single edge pass --------------------------------
__global__ void pass1_kernel(const int* __restrict__ row,
                             const int* __restrict__ col,
                             const float* __restrict__ ew) {
    int e = blockIdx.x * blockDim.x + threadIdx.x;
    if (e >= EE) return;
    int r = row[e], c = col[e];
    float w = (r == c) ? 0.f : ew[e];
    float* deg = (float*)g_degcnt;
    int*   cnt = (int*)(g_degcnt + NPAD);
    if (w != 0.f) atomicAdd(&deg[r], w);
    int slot = atomicAdd(&cnt[c], 1);
    int2 p;
    p.x = r;
    p.y = __float_as_int(w);
    g_pack[c * MAXD + slot] = p;
}

// transform: wn = -rsqrt(deg[r]) * w * rsqrt(deg[c]) in-place; zero stat buffers
__global__ void transform_kernel() {
    int tid = threadIdx.x;
    if (blockIdx.x == 0) {
        for (int i = tid; i < 2 * F1; i += 256) g_stats[i] = 0.f;
        for (int i = tid; i < 2 * F2; i += 256) g_stats2[i] = 0.f;
        for (int i = tid; i < 4 * F2; i += 256) g_bias2[i] = 0.f;
        if (tid < 16) g_biasl[tid] = 0.f;
    }
    int node = (blockIdx.x * blockDim.x + tid) >> 5;
    if (node >= NN) return;
    int lane = tid & 31;
    const float* deg = (const float*)g_degcnt;
    const int*   cnt = (const int*)(g_degcnt + NPAD);
    float dc = deg[node];
    float disc = (dc > 0.f) ? rsqrtf(dc) : 0.f;
    int n = cnt[node];
    int base = node * MAXD;
    for (int i = lane; i < n; i += 32) {
        int2 p = g_pack[base + i];
        float w = __int_as_float(p.y);
        float dr = deg[p.x];
        float disr = (dr > 0.f) ? rsqrtf(dr) : 0.f;
        p.y = __float_as_int(-disr * w * disc);
        g_pack[base + i] = p;
    }
}

// merged converts: x -> TxA block 0, W1 -> W1h
#define XCNT (NN * 32)
#define WCNT (4 * F0 * F1 / 4)
__global__ void cvt_kernel(const float* __restrict__ x, const float* __restrict__ W1) {
    int i = blockIdx.x * blockDim.x + threadIdx.x;
    if (i >= XCNT + WCNT) return;
    const float4* src;
    uint2* dst;
    if (i < XCNT) {
        src = (const float4*)x + i;
        dst = (uint2*)g_TxA + i;
    } else {
        src = (const float4*)W1 + (i - XCNT);
        dst = (uint2*)g_W1h + (i - XCNT);
    }
    float4 v = *src;
    uint2 o;
    __half2 h0 = __floats2half2_rn(v.x, v.y);
    __half2 h1 = __floats2half2_rn(v.z, v.w);
    o.x = *(unsigned*)&h0;
    o.y = *(unsigned*)&h1;
    *dst = o;
}

// ---- gather SPMM (fp16, F=128): out = alpha*(L@in) - sub + add --------------
// Edge metadata distributed via shuffles; 8 gathers in flight.
__device__ __forceinline__ void hfma4(float4& acc, float w, uint2 u) {
    float2 f0 = __half22float2(*(__half2*)&u.x);
    float2 f1 = __half22float2(*(__half2*)&u.y);
    acc.x = fmaf(w, f0.x, acc.x);
    acc.y = fmaf(w, f0.y, acc.y);
    acc.z = fmaf(w, f1.x, acc.z);
    acc.w = fmaf(w, f1.y, acc.w);
}

__global__ void spmm_h(const __half* __restrict__ in, __half* __restrict__ out,
                       const __half* __restrict__ sub,
                       const __half* __restrict__ add, float alpha) {
    int node = (blockIdx.x * blockDim.x + threadIdx.x) >> 5;
    if (node >= NN) return;
    int lane = threadIdx.x & 31;
    int n = ((const int*)(g_degcnt + NPAD))[node];
    const int2* pk = g_pack + node * MAXD;
    const uint2* base = (const uint2*)in + lane;

    float4 acc0 = make_float4(0.f, 0.f, 0.f, 0.f);
    float4 acc1 = make_float4(0.f, 0.f, 0.f, 0.f);
    float4 acc2 = make_float4(0.f, 0.f, 0.f, 0.f);
    float4 acc3 = make_float4(0.f, 0.f, 0.f, 0.f);

    for (int c0 = 0; c0 < n; c0 += 32) {
        int m = n - c0;
        if (m > 32) m = 32;
        // coalesced pack load; inactive lanes padded with (row=0, w=0)
        int2 p = (lane < m) ? pk[c0 + lane] : make_int2(0, 0);
        int mm = (m + 7) & ~7;   // round up; padded edges are harmless (w=0)
#pragma unroll 1
        for (int j = 0; j < mm; j += 8) {
            int r0 = __shfl_sync(0xffffffffu, p.x, j + 0);
            int r1 = __shfl_sync(0xffffffffu, p.x, j + 1);
            int r2 = __shfl_sync(0xffffffffu, p.x, j + 2);
            int r3 = __shfl_sync(0xffffffffu, p.x, j + 3);
            int r4 = __shfl_sync(0xffffffffu, p.x, j + 4);
            int r5 = __shfl_sync(0xffffffffu, p.x, j + 5);
            int r6 = __shfl_sync(0xffffffffu, p.x, j + 6);
            int r7 = __shfl_sync(0xffffffffu, p.x, j + 7);
            uint2 u0 = base[(size_t)r0 * 32];
            uint2 u1 = base[(size_t)r1 * 32];
            uint2 u2 = base[(size_t)r2 * 32];
            uint2 u3 = base[(size_t)r3 * 32];
            uint2 u4 = base[(size_t)r4 * 32];
            uint2 u5 = base[(size_t)r5 * 32];
            uint2 u6 = base[(size_t)r6 * 32];
            uint2 u7 = base[(size_t)r7 * 32];
            float w0 = __int_as_float(__shfl_sync(0xffffffffu, p.y, j + 0));
            float w1 = __int_as_float(__shfl_sync(0xffffffffu, p.y, j + 1));
            float w2 = __int_as_float(__shfl_sync(0xffffffffu, p.y, j + 2));
            float w3 = __int_as_float(__shfl_sync(0xffffffffu, p.y, j + 3));
            float w4 = __int_as_float(__shfl_sync(0xffffffffu, p.y, j + 4));
            float w5 = __int_as_float(__shfl_sync(0xffffffffu, p.y, j + 5));
            float w6 = __int_as_float(__shfl_sync(0xffffffffu, p.y, j + 6));
            float w7 = __int_as_float(__shfl_sync(0xffffffffu, p.y, j + 7));
            hfma4(acc0, w0, u0);
            hfma4(acc1, w1, u1);
            hfma4(acc2, w2, u2);
            hfma4(acc3, w3, u3);
            hfma4(acc0, w4, u4);
            hfma4(acc1, w5, u5);
            hfma4(acc2, w6, u6);
            hfma4(acc3, w7, u7);
        }
    }
    float4 r;
    r.x = alpha * ((acc0.x + acc1.x) + (acc2.x + acc3.x));
    r.y = alpha * ((acc0.y + acc1.y) + (acc2.y + acc3.y));
    r.z = alpha * ((acc0.z + acc1.z) + (acc2.z + acc3.z));
    r.w = alpha * ((acc0.w + acc1.w) + (acc2.w + acc3.w));
    size_t oidx = (size_t)node * 32 + lane;
    if (add) {
        uint2 u = ((const uint2*)add)[oidx];
        float2 f0 = __half22float2(*(__half2*)&u.x);
        float2 f1 = __half22float2(*(__half2*)&u.y);
        r.x += f0.x; r.y += f0.y; r.z += f1.x; r.w += f1.y;
    }
    if (sub) {
        uint2 u = ((const uint2*)sub)[oidx];
        float2 f0 = __half22float2(*(__half2*)&u.x);
        float2 f1 = __half22float2(*(__half2*)&u.y);
        r.x -= f0.x; r.y -= f0.y; r.z -= f1.x; r.w -= f1.y;
    }
    uint2 o;
    __half2 h0 = __floats2half2_rn(r.x, r.y);
    __half2 h1 = __floats2half2_rn(r.z, r.w);
    o.x = *(unsigned*)&h0;
    o.y = *(unsigned*)&h1;
    ((uint2*)out)[oidx] = o;
}

// ---------------- fp16 tensor-core GEMMs, cp.async double-buffered -----------
#define PA 40
#define PB 136
#define ASTG (128 * PA)
#define BSTG (32 * PB)

__device__ __forceinline__ void cp16(unsigned sdst, const void* gsrc) {
    asm volatile("cp.async.cg.shared.global [%0], [%1], 16;" :: "r"(sdst), "l"(gsrc));
}

// GEMM1: out1(h) = relu( sum_chunk TxA_chunk @ W1h_chunk + b1 ) ; fused BN1 stats
__global__ __launch_bounds__(256)
void gemm1_f16(const __half* __restrict__ A, const float* __restrict__ bias,
               __half* __restrict__ C) {
    __shared__ __align__(16) __half As[2 * ASTG];
    __shared__ __align__(16) __half Bs[2 * BSTG];
    __shared__ float sS[128], sQ[128];

    const int tid = threadIdx.x;
    const int lane = tid & 31;
    const int wid = tid >> 5;
    const int warp_m = wid >> 2;
    const int warp_n = wid & 3;
    const int bm = blockIdx.x * 128;
    const int bn = blockIdx.y * 128;
    const int NIT = 16;

    if (tid < 128) { sS[tid] = 0.f; sQ[tid] = 0.f; }

    float acc[4][4][4];
#pragma unroll
    for (int i = 0; i < 4; i++)
#pragma unroll
        for (int j = 0; j < 4; j++)
#pragma unroll
            for (int q = 0; q < 4; q++) acc[i][j][q] = 0.f;

    const unsigned asBase0 = (unsigned)__cvta_generic_to_shared(As);
    const unsigned bsBase0 = (unsigned)__cvta_generic_to_shared(Bs);
    const unsigned asFrag = asBase0 +
        ((warp_m * 64 + (lane & 15)) * PA + (lane >> 4) * 8) * 2;
    const int b_k = ((lane >> 3) & 1) * 8 + (lane & 7);
    const int b_n = (lane >> 4) * 8;

    auto load_tiles = [&](int st, int it) {
        int chunk = it >> 2;
        int k0 = (it & 3) * 32;
        const __half* Ab = A + (size_t)chunk * NPAD * F0 + (size_t)bm * F0 + k0;
        const __half* Wb = g_W1h + (size_t)chunk * F0 * F1 + (size_t)k0 * F1 + bn;
        unsigned sA = asBase0 + st * ASTG * 2;
        unsigned sB = bsBase0 + st * BSTG * 2;
#pragma unroll
        for (int p = 0; p < 2; ++p) {
            int idx = p * 256 + tid;
            int rrow = idx >> 2, ch = (idx & 3) * 8;
            cp16(sA + (rrow * PA + ch) * 2, Ab + (size_t)rrow * F0 + ch);
            int kr = idx >> 4, bc = (idx & 15) * 8;
            cp16(sB + (kr * PB + bc) * 2, Wb + (size_t)kr * F1 + bc);
        }
        asm volatile("cp.async.commit_group;");
    };

    load_tiles(0, 0);
    int st = 0;
#pragma unroll 1
    for (int it = 0; it < NIT; ++it) {
        if (it + 1 < NIT) {
            load_tiles(st ^ 1, it + 1);
            asm volatile("cp.async.wait_group 1;");
        } else {
            asm volatile("cp.async.wait_group 0;");
        }
        __syncthreads();
#pragma unroll
        for (int ks = 0; ks < 2; ++ks) {
            unsigned a[4][4];
#pragma unroll
            for (int ms = 0; ms < 4; ++ms) {
                unsigned addr = asFrag + st * ASTG * 2 + ms * (16 * PA * 2) + ks * 32;
                asm volatile(
                    "ldmatrix.sync.aligned.m8n8.x4.shared.b16 {%0,%1,%2,%3}, [%4];"
                    : "=r"(a[ms][0]), "=r"(a[ms][1]), "=r"(a[ms][2]), "=r"(a[ms][3])
                    : "r"(addr));
            }
            unsigned b[4][2];
#pragma unroll
            for (int nsp = 0; nsp < 2; ++nsp) {
                int ncol = warp_n * 32 + nsp * 16 + b_n;
                unsigned baddr = bsBase0 + st * BSTG * 2 +
                                 ((ks * 16 + b_k) * PB + ncol) * 2;
                asm volatile(
                    "ldmatrix.sync.aligned.m8n8.x4.trans.shared.b16 {%0,%1,%2,%3}, [%4];"
                    : "=r"(b[2 * nsp][0]), "=r"(b[2 * nsp][1]),
                      "=r"(b[2 * nsp + 1][0]), "=r"(b[2 * nsp + 1][1])
                    : "r"(baddr));
            }
#pragma unroll
            for (int ms = 0; ms < 4; ++ms)
#pragma unroll
                for (int ns = 0; ns < 4; ++ns) {
                    asm volatile(
                        "mma.sync.aligned.m16n8k16.row.col.f32.f16.f16.f32 "
                        "{%0,%1,%2,%3}, {%4,%5,%6,%7}, {%8,%9}, {%0,%1,%2,%3};"
                        : "+f"(acc[ms][ns][0]), "+f"(acc[ms][ns][1]),
                          "+f"(acc[ms][ns][2]), "+f"(acc[ms][ns][3])
                        : "r"(a[ms][0]), "r"(a[ms][1]), "r"(a[ms][2]), "r"(a[ms][3]),
                          "r"(b[ns][0]), "r"(b[ns][1]));
                }
        }
        __syncthreads();
        st ^= 1;
    }

    float s[4][2], q[4][2];
#pragma unroll
    for (int ns = 0; ns < 4; ++ns) { s[ns][0] = s[ns][1] = q[ns][0] = q[ns][1] = 0.f; }
#pragma unroll
    for (int ms = 0; ms < 4; ++ms) {
        int r0 = bm + warp_m * 64 + ms * 16 + (lane >> 2);
        bool ok0 = r0 < NN, ok1 = (r0 + 8) < NN;
#pragma unroll
        for (int ns = 0; ns < 4; ++ns) {
            int cc = bn + warp_n * 32 + ns * 8 + 2 * (lane & 3);
            float a0 = fmaxf(acc[ms][ns][0] + bias[cc + 0], 0.f);
            float a1 = fmaxf(acc[ms][ns][1] + bias[cc + 1], 0.f);
            float a2 = fmaxf(acc[ms][ns][2] + bias[cc + 0], 0.f);
            float a3 = fmaxf(acc[ms][ns][3] + bias[cc + 1], 0.f);
            __half2 h0 = __floats2half2_rn(a0, a1);
            __half2 h1 = __floats2half2_rn(a2, a3);
            *(__half2*)&C[(size_t)r0 * F1 + cc] = h0;
            *(__half2*)&C[(size_t)(r0 + 8) * F1 + cc] = h1;
            float m0 = ok0 ? a0 : 0.f;
            float m1 = ok0 ? a1 : 0.f;
            float m2 = ok1 ? a2 : 0.f;
            float m3 = ok1 ? a3 : 0.f;
            s[ns][0] += m0 + m2;
            s[ns][1] += m1 + m3;
            q[ns][0] += m0 * m0 + m2 * m2;
            q[ns][1] += m1 * m1 + m3 * m3;
        }
    }
#pragma unroll
    for (int ns = 0; ns < 4; ++ns)
#pragma unroll
        for (int par = 0; par < 2; ++par) {
            float sv = s[ns][par], qv = q[ns][par];
            sv += __shfl_xor_sync(0xffffffffu, sv, 4);
            sv += __shfl_xor_sync(0xffffffffu, sv, 8);
            sv += __shfl_xor_sync(0xffffffffu, sv, 16);
            qv += __shfl_xor_sync(0xffffffffu, qv, 4);
            qv += __shfl_xor_sync(0xffffffffu, qv, 8);
            qv += __shfl_xor_sync(0xffffffffu, qv, 16);
            if (lane < 4) {
                int colL = warp_n * 32 + ns * 8 + 2 * lane + par;
                atomicAdd(&sS[colL], sv);
                atomicAdd(&sQ[colL], qv);
            }
        }
    __syncthreads();
    if (tid < 128) {
        atomicAdd(&g_stats[bn + tid], sS[tid]);
        atomicAdd(&g_stats[F1 + bn + tid], sQ[tid]);
    }
}

// prep2: W2h = sc ⊙ W2c (Horner precombine fused), bias2 = sh @ W2c_k (+ b2)
__global__ void prep2_kernel(const float* __restrict__ W2, const float* __restrict__ b2,
                             const float* __restrict__ gamma, const float* __restrict__ beta) {
    int i = blockIdx.x * blockDim.x + threadIdx.x;
    const int SZ = F1 * F2;
    if (i >= SZ) return;
    int ch = i >> 7;
    int j = i & 127;
    float w0 = W2[i], w1 = W2[SZ + i], w2 = W2[2 * SZ + i], w3 = W2[3 * SZ + i];
    float c0 = w0 - w2;
    float c1 = w1 - 3.f * w3;
    float c2 = 2.f * w2;
    float c3 = 4.f * w3;
    float m = g_stats[ch] * (1.f / NN);
    float v = g_stats[F1 + ch] * (1.f / NN) - m * m;
    float inv = rsqrtf(v + 1e-5f);
    float sc = gamma[ch] * inv;
    float sh = beta[ch] - m * sc;
    g_W2h[i]          = __float2half(c0 * sc);
    g_W2h[SZ + i]     = __float2half(c1 * sc);
    g_W2h[2 * SZ + i] = __float2half(c2 * sc);
    g_W2h[3 * SZ + i] = __float2half(c3 * sc);
    atomicAdd(&g_bias2[j],           sh * c0 + ((ch == 0) ? b2[j] : 0.f));
    atomicAdd(&g_bias2[F2 + j],      sh * c1);
    atomicAdd(&g_bias2[2 * F2 + j],  sh * c2);
    atomicAdd(&g_bias2[3 * F2 + j],  sh * c3);
}

// GEMM2: C_k(h) = relu(out1) @ W2h_k + bias2_k ; k = blockIdx.y
__global__ __launch_bounds__(256)
void gemm2_f16(const __half* __restrict__ A) {
    __shared__ __align__(16) __half As[2 * ASTG];
    __shared__ __align__(16) __half Bs[2 * BSTG];

    const int tid = threadIdx.x;
    const int lane = tid & 31;
    const int wid = tid >> 5;
    const int warp_m = wid >> 2;
    const int warp_n = wid & 3;
    const int bm = blockIdx.x * 128;
    const int kblk = blockIdx.y;
    const __half* Wb0 = g_W2h + (size_t)kblk * F1 * F2;
    __half* C = g_Ck + (size_t)kblk * NPAD * F2;
    const int NIT = 8;

    float acc[4][4][4];
#pragma unroll
    for (int i = 0; i < 4; i++)
#pragma unroll
        for (int j = 0; j < 4; j++)
#pragma unroll
            for (int q = 0; q < 4; q++) acc[i][j][q] = 0.f;

    const unsigned asBase0 = (unsigned)__cvta_generic_to_shared(As);
    const unsigned bsBase0 = (unsigned)__cvta_generic_to_shared(Bs);
    const unsigned asFrag = asBase0 +
        ((warp_m * 64 + (lane & 15)) * PA + (lane >> 4) * 8) * 2;
    const int b_k = ((lane >> 3) & 1) * 8 + (lane & 7);
    const int b_n = (lane >> 4) * 8;

    auto load_tiles = [&](int st, int it) {
        int k0 = it * 32;
        const __half* Ab = A + (size_t)bm * F1 + k0;
        const __half* Wb = Wb0 + (size_t)k0 * F2;
        unsigned sA = asBase0 + st * ASTG * 2;
        unsigned sB = bsBase0 + st * BSTG * 2;
#pragma unroll
        for (int p = 0; p < 2; ++p) {
            int idx = p * 256 + tid;
            int rrow = idx >> 2, ch = (idx & 3) * 8;
            cp16(sA + (rrow * PA + ch) * 2, Ab + (size_t)rrow * F1 + ch);
            int kr = idx >> 4, bc = (idx & 15) * 8;
            cp16(sB + (kr * PB + bc) * 2, Wb + (size_t)kr * F2 + bc);
        }
        asm volatile("cp.async.commit_group;");
    };

    load_tiles(0, 0);
    int st = 0;
#pragma unroll 1
    for (int it = 0; it < NIT; ++it) {
        if (it + 1 < NIT) {
            load_tiles(st ^ 1, it + 1);
            asm volatile("cp.async.wait_group 1;");
        } else {
            asm volatile("cp.async.wait_group 0;");
        }
        __syncthreads();
#pragma unroll
        for (int ks = 0; ks < 2; ++ks) {
            unsigned a[4][4];
#pragma unroll
            for (int ms = 0; ms < 4; ++ms) {
                unsigned addr = asFrag + st * ASTG * 2 + ms * (16 * PA * 2) + ks * 32;
                asm volatile(
                    "ldmatrix.sync.aligned.m8n8.x4.shared.b16 {%0,%1,%2,%3}, [%4];"
                    : "=r"(a[ms][0]), "=r"(a[ms][1]), "=r"(a[ms][2]), "=r"(a[ms][3])
                    : "r"(addr));
            }
            unsigned b[4][2];
#pragma unroll
            for (int nsp = 0; nsp < 2; ++nsp) {
                int ncol = warp_n * 32 + nsp * 16 + b_n;
                unsigned baddr = bsBase0 + st * BSTG * 2 +
                                 ((ks * 16 + b_k) * PB + ncol) * 2;
                asm volatile(
                    "ldmatrix.sync.aligned.m8n8.x4.trans.shared.b16 {%0,%1,%2,%3}, [%4];"
                    : "=r"(b[2 * nsp][0]), "=r"(b[2 * nsp][1]),
                      "=r"(b[2 * nsp + 1][0]), "=r"(b[2 * nsp + 1][1])
                    : "r"(baddr));
            }
#pragma unroll
            for (int ms = 0; ms < 4; ++ms)
#pragma unroll
                for (int ns = 0; ns < 4; ++ns) {
                    asm volatile(
                        "mma.sync.aligned.m16n8k16.row.col.f32.f16.f16.f32 "
                        "{%0,%1,%2,%3}, {%4,%5,%6,%7}, {%8,%9}, {%0,%1,%2,%3};"
                        : "+f"(acc[ms][ns][0]), "+f"(acc[ms][ns][1]),
                          "+f"(acc[ms][ns][2]), "+f"(acc[ms][ns][3])
                        : "r"(a[ms][0]), "r"(a[ms][1]), "r"(a[ms][2]), "r"(a[ms][3]),
                          "r"(b[ns][0]), "r"(b[ns][1]));
                }
        }
        __syncthreads();
        st ^= 1;
    }

#pragma unroll
    for (int ms = 0; ms < 4; ++ms) {
        int r0 = bm + warp_m * 64 + ms * 16 + (lane >> 2);
#pragma unroll
        for (int ns = 0; ns < 4; ++ns) {
            int cc = warp_n * 32 + ns * 8 + 2 * (lane & 3);
            float bx = g_bias2[kblk * F2 + cc + 0];
            float by = g_bias2[kblk * F2 + cc + 1];
            __half2 h0 = __floats2half2_rn(acc[ms][ns][0] + bx, acc[ms][ns][1] + by);
            __half2 h1 = __floats2half2_rn(acc[ms][ns][2] + bx, acc[ms][ns][3] + by);
            *(__half2*)&C[(size_t)r0 * F2 + cc] = h0;
            *(__half2*)&C[(size_t)(r0 + 8) * F2 + cc] = h1;
        }
    }
}

// ---------------- BN2 stats ---------------------------------------------------
__global__ void stats_h128(const __half* __restrict__ X) {
    int col = threadIdx.x & 127;
    int ro = threadIdx.x >> 7;
    int r0 = blockIdx.x * 128 + ro;
    int rend = blockIdx.x * 128 + 128;
    if (rend > NN) rend = NN;
    float s = 0.f, s2 = 0.f;
    for (int r = r0; r < rend; r += 2) {
        float v = __half2float(X[(size_t)r * F2 + col]);
        v = v > 0.f ? v : 0.f;
        s += v;
        s2 = fmaf(v, v, s2);
    }
    atomicAdd(&g_stats2[col], s);
    atomicAdd(&g_stats2[F2 + col], s2);
}

// prep3: fold BN2 into final linear
__global__ void prep3_kernel(const float* __restrict__ Wl, const float* __restrict__ bl,
                             const float* __restrict__ gamma, const float* __restrict__ beta) {
    int c = threadIdx.x;    // 128 threads
    float m = g_stats2[c] * (1.f / NN);
    float v = g_stats2[F2 + c] * (1.f / NN) - m * m;
    float inv = rsqrtf(v + 1e-5f);
    float sc = gamma[c] * inv;
    float sh = beta[c] - m * sc;
#pragma unroll
    for (int o = 0; o < 10; ++o) {
        float w = Wl[o * F2 + c];
        g_Wlh[o * F2 + c] = w * sc;
        float p = sh * w;
        p += __shfl_xor_sync(0xffffffffu, p, 16);
        p += __shfl_xor_sync(0xffffffffu, p, 8);
        p += __shfl_xor_sync(0xffffffffu, p, 4);
        p += __shfl_xor_sync(0xffffffffu, p, 2);
        p += __shfl_xor_sync(0xffffffffu, p, 1);
        if ((c & 31) == 0) atomicAdd(&g_biasl[o], p);
    }
    if (c < 10) atomicAdd(&g_biasl[c], bl[c]);
}

// final: out = relu(out2) @ Wlh^T + biasl, warp per node
__global__ void final_kernel(const __half* __restrict__ h, float* __restrict__ out) {
    int node = (blockIdx.x * blockDim.x + threadIdx.x) >> 5;
    if (node >= NN) return;
    int lane = threadIdx.x & 31;
    uint2 u = ((const uint2*)(h + (size_t)node * F2))[lane];
    float2 f0 = __half22float2(*(__half2*)&u.x);
    float2 f1 = __half22float2(*(__half2*)&u.y);
    float h0 = fmaxf(f0.x, 0.f);
    float h1 = fmaxf(f0.y, 0.f);
    float h2 = fmaxf(f1.x, 0.f);
    float h3 = fmaxf(f1.y, 0.f);
#pragma unroll
    for (int o = 0; o < 10; ++o) {
        float4 w = ((const float4*)(g_Wlh + o * F2))[lane];
        float p = h0 * w.x + h1 * w.y + h2 * w.z + h3 * w.w;
        p += __shfl_xor_sync(0xffffffffu, p, 16);
        p += __shfl_xor_sync(0xffffffffu, p, 8);
        p += __shfl_xor_sync(0xffffffffu, p, 4);
        p += __shfl_xor_sync(0xffffffffu, p, 2);
        p += __shfl_xor_sync(0xffffffffu, p, 1);
        if (lane == 0) out[node * 10 + o] = p + g_biasl[o];
    }
}

// ---------------- launch ------------------------------------------------------
extern "C" void kernel_launch(void* const* d_in, const int* in_sizes, int n_in,
                              void* d_out, int out_size) {
    const float* x      = (const float*)d_in[0];
    const int*   ei     = (const int*)d_in[1];
    const float* ew     = (const float*)d_in[2];
    const float* W1     = (const float*)d_in[3];
    const float* b1     = (const float*)d_in[4];
    const float* W2     = (const float*)d_in[5];
    const float* b2     = (const float*)d_in[6];
    const float* gamma1 = (const float*)d_in[7];
    const float* beta1  = (const float*)d_in[8];
    const float* gamma2 = (const float*)d_in[9];
    const float* beta2  = (const float*)d_in[10];
    const float* Wlin   = (const float*)d_in[11];
    const float* blin   = (const float*)d_in[12];
    float* out = (float*)d_out;

    const int* row = ei;
    const int* col = ei + EE;

    unsigned* degcnt;
    __half *TxA, *out1, *Ck, *out2;
    cudaGetSymbolAddress((void**)&degcnt, g_degcnt);
    cudaGetSymbolAddress((void**)&TxA,  g_TxA);
    cudaGetSymbolAddress((void**)&out1, g_out1);
    cudaGetSymbolAddress((void**)&Ck,   g_Ck);
    cudaGetSymbolAddress((void**)&out2, g_out2);

    const int EB = (EE + 255) / 256;
    const int SB = (NN * 32 + 255) / 256;

    // ---- ELL build ----
    cudaMemsetAsync(degcnt, 0, 2 * NPAD * sizeof(unsigned));
    pass1_kernel<<<EB, 256>>>(row, col, ew);
    transform_kernel<<<SB, 256>>>();
    cvt_kernel<<<(XCNT + WCNT + 255) / 256, 256>>>(x, W1);

    // ---- layer 1: Chebyshev recursion at F=128 (fp16 features) ----
    __half* A0 = TxA;
    __half* A1 = TxA + (size_t)NPAD * F0;
    __half* A2 = TxA + (size_t)2 * NPAD * F0;
    __half* A3 = TxA + (size_t)3 * NPAD * F0;
    spmm_h<<<SB, 256>>>(A0, A1, nullptr, nullptr, 1.f);
    spmm_h<<<SB, 256>>>(A1, A2, A0, nullptr, 2.f);
    spmm_h<<<SB, 256>>>(A2, A3, A1, nullptr, 2.f);

    gemm1_f16<<<dim3(NPAD / 128, 2), 256>>>(TxA, b1, out1);

    // ---- layer 2: Horner form with BN folded into weights ----
    prep2_kernel<<<(F1 * F2 + 255) / 256, 256>>>(W2, b2, gamma1, beta1);
    gemm2_f16<<<dim3(NPAD / 128, 4), 256>>>(out1);

    __half* C0 = Ck;
    __half* C1 = Ck + (size_t)NPAD * F2;
    __half* C2 = Ck + (size_t)2 * NPAD * F2;
    __half* C3 = Ck + (size_t)3 * NPAD * F2;
    __half* t1 = TxA;
    __half* t2 = TxA + (size_t)NPAD * F0;
    spmm_h<<<SB, 256>>>(C3, t1, nullptr, C2, 1.f);
    spmm_h<<<SB, 256>>>(t1, t2, nullptr, C1, 1.f);
    spmm_h<<<SB, 256>>>(t2, out2, nullptr, C0, 1.f);

    stats_h128<<<157, 256>>>(out2);
    prep3_kernel<<<1, 128>>>(Wlin, blin, gamma2, beta2);

    final_kernel<<<SB, 256>>>(out2, out);
}